// round 3
// baseline (speedup 1.0000x reference)
#include <cuda_runtime.h>
#include <math.h>

#define HG 200
#define WG 704
#define HWG (HG*WG)
#define CC 256
#define NBOX 128

// ---------------- scratch (device globals: allocation-free) ----------------
__device__ float    g_A[HWG*CC];          // feature map buffer A (NHWC)
__device__ float    g_B[HWG*CC];          // feature map buffer B (NHWC)
__device__ float    g_obj[NBOX*CC];       // per-box MLP output
__device__ unsigned g_mask[HWG*4];        // per-cell 128-bit box mask
__device__ float    g_wr[6*9*CC*CC];      // repacked weights [conv][tap][ci][co]
__device__ float    g_scale[6*CC];        // BN fused scale
__device__ float    g_bias[6*CC];         // BN fused bias

// ---------------- small prep kernels ----------------
__global__ void zero_mask_kernel() {
    int i = blockIdx.x * blockDim.x + threadIdx.x;
    int tot = HWG * 4;
    for (; i < tot; i += gridDim.x * blockDim.x) g_mask[i] = 0u;
}

// conv_w: (3,2,Cout,Cin,3,3) OIHW  ->  g_wr: [conv][tap][ci][co]
__global__ void repack_kernel(const float* __restrict__ cw) {
    int i = blockIdx.x * blockDim.x + threadIdx.x;
    if (i >= 6 * 9 * CC * CC) return;
    int co  = i & 255;
    int ci  = (i >> 8) & 255;
    int t9  = i >> 16;
    int tap = t9 % 9;
    int cv  = t9 / 9;
    g_wr[i] = cw[((cv * CC + co) * CC + ci) * 9 + tap];
}

__global__ void bnprep_kernel(const float* __restrict__ g, const float* __restrict__ b,
                              const float* __restrict__ m, const float* __restrict__ v) {
    int i = blockIdx.x * 256 + threadIdx.x;   // 6 blocks x 256
    float inv = g[i] / sqrtf(v[i] + 1e-5f);
    g_scale[i] = inv;
    g_bias[i]  = b[i] - m[i] * inv;
}

// ---------------- MLP: obj[n][c] ----------------
__global__ void mlp_kernel(const float* __restrict__ box, const float* __restrict__ score,
                           const float* __restrict__ w1, const float* __restrict__ b1,
                           const float* __restrict__ w2, const float* __restrict__ b2,
                           const float* __restrict__ w3, const float* __restrict__ b3) {
    int n = blockIdx.x;
    int c = threadIdx.x;
    __shared__ float feat[25];
    __shared__ float h1[CC];
    __shared__ float h2[CC];
    if (c < 24) feat[c] = box[n * 24 + c];
    if (c == 24) feat[24] = score[n];
    __syncthreads();
    float s = b1[c];
    #pragma unroll
    for (int k = 0; k < 25; k++) s += feat[k] * w1[k * CC + c];
    h1[c] = fmaxf(s, 0.f);
    __syncthreads();
    s = b2[c];
    for (int k = 0; k < CC; k++) s += h1[k] * w2[k * CC + c];
    h2[c] = fmaxf(s, 0.f);
    __syncthreads();
    s = b3[c];
    for (int k = 0; k < CC; k++) s += h2[k] * w3[k * CC + c];
    g_obj[n * CC + c] = s * score[n];
}

// ---------------- rasterize boxes into bitmask ----------------
__global__ void raster_kernel(const float* __restrict__ box) {
    int n = blockIdx.x;
    __shared__ float ax[4], ay[4], vx[4], vy[4];
    __shared__ int ilo, ihi, jlo, jhi;
    if (threadIdx.x == 0) {
        float gx[4], gy[4];
        float minx = 1e30f, maxx = -1e30f, miny = 1e30f, maxy = -1e30f;
        for (int e = 0; e < 4; e++) {
            gx[e] = (box[n * 24 + e * 3 + 0] - (-140.8f)) / 0.4f;
            gy[e] = (box[n * 24 + e * 3 + 1] - (-40.0f)) / 0.4f;
            minx = fminf(minx, gx[e]); maxx = fmaxf(maxx, gx[e]);
            miny = fminf(miny, gy[e]); maxy = fmaxf(maxy, gy[e]);
        }
        for (int e = 0; e < 4; e++) {
            ax[e] = gx[e]; ay[e] = gy[e];
            vx[e] = gx[(e + 1) & 3] - gx[e];
            vy[e] = gy[(e + 1) & 3] - gy[e];
        }
        int a = (int)floorf(minx - 0.5f); jlo = a < 0 ? 0 : a;
        int bq = (int)ceilf(maxx - 0.5f); jhi = bq > WG - 1 ? WG - 1 : bq;
        int c = (int)floorf(miny - 0.5f); ilo = c < 0 ? 0 : c;
        int d = (int)ceilf(maxy - 0.5f);  ihi = d > HG - 1 ? HG - 1 : d;
    }
    __syncthreads();
    int wspan = jhi - jlo + 1, hspan = ihi - ilo + 1;
    if (wspan <= 0 || hspan <= 0) return;
    int tot = wspan * hspan;
    unsigned bit = 1u << (n & 31);
    int word = n >> 5;
    for (int t = threadIdx.x; t < tot; t += blockDim.x) {
        int i = ilo + t / wspan;
        int j = jlo + t % wspan;
        float cx = j + 0.5f, cy = i + 0.5f;
        bool ins = true;
        #pragma unroll
        for (int e = 0; e < 4; e++) {
            float cr = vx[e] * (cy - ay[e]) - vy[e] * (cx - ax[e]);
            ins = ins && (cr >= 0.f);
        }
        if (ins) atomicOr(&g_mask[(i * WG + j) * 4 + word], bit);
    }
}

// ---------------- scatter: build x0 (NHWC) into g_A ----------------
__global__ void scatter_kernel() {
    int c = threadIdx.x;
    for (int cell = blockIdx.x; cell < HWG; cell += gridDim.x) {
        unsigned m[4];
        m[0] = g_mask[cell * 4 + 0];
        m[1] = g_mask[cell * 4 + 1];
        m[2] = g_mask[cell * 4 + 2];
        m[3] = g_mask[cell * 4 + 3];
        int cnt = __popc(m[0]) + __popc(m[1]) + __popc(m[2]) + __popc(m[3]);
        float s = 0.f;
        if (cnt) {
            #pragma unroll
            for (int w = 0; w < 4; w++) {
                unsigned bits = m[w];
                while (bits) {
                    int b = __ffs(bits) - 1;
                    bits &= bits - 1;
                    s += g_obj[(w * 32 + b) * CC + c];
                }
            }
            s = s / (float)cnt;
        }
        g_A[cell * CC + c] = s;
    }
}

// ---------------- conv3x3 + BN (+residual) + ReLU, NHWC fp32 ----------------
// Block tile: 8x8 pixels x 64 cout. Threads 256 = 16(co) x 16(pix-group).
// Each thread: 4 pixels (one row) x 4 couts.
__global__ void __launch_bounds__(256) conv_kernel(int cidx, int second) {
    const float* __restrict__ in  = second ? g_B : g_A;
    float*       __restrict__ out = second ? g_A : g_B;
    const float* __restrict__ wr  = g_wr + cidx * 9 * CC * CC;

    __shared__ __align__(16) float sIn[10][10][16];
    __shared__ __align__(16) float sW[9][16][64];

    int tid = threadIdx.x;
    int tx  = tid & 15;       // cout group
    int ty  = tid >> 4;       // pixel group
    int w0  = blockIdx.x * 8;
    int h0  = blockIdx.y * 8;
    int co0 = blockIdx.z * 64;
    int phb = ty >> 1;
    int pwb = (ty & 1) * 4;

    float acc[4][4];
    #pragma unroll
    for (int k = 0; k < 4; k++)
        #pragma unroll
        for (int c = 0; c < 4; c++) acc[k][c] = 0.f;

    for (int ci0 = 0; ci0 < CC; ci0 += 16) {
        // stage input halo tile 10x10x16
        for (int idx = tid; idx < 400; idx += 256) {
            int pos = idx >> 2, c4 = idx & 3;
            int hh = pos / 10, ww = pos - hh * 10;
            int gh = h0 + hh - 1, gw = w0 + ww - 1;
            float4 v = make_float4(0.f, 0.f, 0.f, 0.f);
            if (gh >= 0 && gh < HG && gw >= 0 && gw < WG)
                v = *(const float4*)&in[(gh * WG + gw) * CC + ci0 + c4 * 4];
            *(float4*)&sIn[hh][ww][c4 * 4] = v;
        }
        // stage weights 9x16x64
        for (int idx = tid; idx < 2304; idx += 256) {
            int co4 = idx & 15;
            int r   = idx >> 4;
            int ci  = r & 15;
            int tap = r >> 4;
            float4 v = *(const float4*)&wr[(tap * CC + ci0 + ci) * CC + co0 + co4 * 4];
            *(float4*)&sW[tap][ci][co4 * 4] = v;
        }
        __syncthreads();
        #pragma unroll 4
        for (int ci = 0; ci < 16; ci++) {
            #pragma unroll
            for (int tap = 0; tap < 9; tap++) {
                int dh = tap / 3, dw = tap - dh * 3;
                float4 wv = *(const float4*)&sW[tap][ci][tx * 4];
                #pragma unroll
                for (int k = 0; k < 4; k++) {
                    float xv = sIn[phb + dh][pwb + k + dw][ci];
                    acc[k][0] += xv * wv.x;
                    acc[k][1] += xv * wv.y;
                    acc[k][2] += xv * wv.z;
                    acc[k][3] += xv * wv.w;
                }
            }
        }
        __syncthreads();
    }

    float4 sc = *(const float4*)&g_scale[cidx * CC + co0 + tx * 4];
    float4 bs = *(const float4*)&g_bias [cidx * CC + co0 + tx * 4];
    #pragma unroll
    for (int k = 0; k < 4; k++) {
        int gh = h0 + phb, gw = w0 + pwb + k;
        int off = (gh * WG + gw) * CC + co0 + tx * 4;
        float4 v;
        v.x = acc[k][0] * sc.x + bs.x;
        v.y = acc[k][1] * sc.y + bs.y;
        v.z = acc[k][2] * sc.z + bs.z;
        v.w = acc[k][3] * sc.w + bs.w;
        if (second) {
            float4 r = *(const float4*)&g_A[off];   // residual (in-place safe: same thread)
            v.x += r.x; v.y += r.y; v.z += r.z; v.w += r.w;
        }
        v.x = fmaxf(v.x, 0.f); v.y = fmaxf(v.y, 0.f);
        v.z = fmaxf(v.z, 0.f); v.w = fmaxf(v.w, 0.f);
        *(float4*)&out[off] = v;
    }
}

// ---------------- NHWC -> CHW final transpose ----------------
__global__ void transpose_kernel(float* __restrict__ out) {
    __shared__ float t[32][33];
    int h  = blockIdx.z;
    int w0 = blockIdx.x * 32;
    int c0 = blockIdx.y * 32;
    #pragma unroll
    for (int r = 0; r < 4; r++) {
        int ww = threadIdx.y + r * 8;
        t[ww][threadIdx.x] = g_A[(h * WG + w0 + ww) * CC + c0 + threadIdx.x];
    }
    __syncthreads();
    #pragma unroll
    for (int r = 0; r < 4; r++) {
        int cc = threadIdx.y + r * 8;
        out[(c0 + cc) * HWG + h * WG + w0 + threadIdx.x] = t[threadIdx.x][cc];
    }
}

// ---------------- launch ----------------
extern "C" void kernel_launch(void* const* d_in, const int* in_sizes, int n_in,
                              void* d_out, int out_size) {
    const float* box    = (const float*)d_in[0];
    const float* score  = (const float*)d_in[1];
    const float* w1     = (const float*)d_in[2];
    const float* b1     = (const float*)d_in[3];
    const float* w2     = (const float*)d_in[4];
    const float* b2     = (const float*)d_in[5];
    const float* w3     = (const float*)d_in[6];
    const float* b3     = (const float*)d_in[7];
    const float* conv_w = (const float*)d_in[8];
    const float* bng    = (const float*)d_in[9];
    const float* bnb    = (const float*)d_in[10];
    const float* bnm    = (const float*)d_in[11];
    const float* bnv    = (const float*)d_in[12];
    float* out = (float*)d_out;

    zero_mask_kernel<<<550, 1024>>>();
    repack_kernel<<<(6 * 9 * CC * CC + 255) / 256, 256>>>(conv_w);
    bnprep_kernel<<<6, 256>>>(bng, bnb, bnm, bnv);
    mlp_kernel<<<NBOX, 256>>>(box, score, w1, b1, w2, b2, w3, b3);
    raster_kernel<<<NBOX, 256>>>(box);
    scatter_kernel<<<4096, 256>>>();

    for (int c = 0; c < 6; c++) {
        conv_kernel<<<dim3(WG / 8, HG / 8, 4), 256>>>(c, c & 1);
    }
    transpose_kernel<<<dim3(WG / 32, CC / 32, HG), dim3(32, 8)>>>(out);
}

// round 4
// speedup vs baseline: 1.0017x; 1.0017x over previous
#include <cuda_runtime.h>
#include <math.h>

#define HG 200
#define WG 704
#define HWG (HG*WG)
#define CC 256
#define NBOX 128

// ---------------- scratch (device globals: allocation-free) ----------------
__device__ float    g_A[HWG*CC];          // feature map buffer A (NHWC)
__device__ float    g_B[HWG*CC];          // feature map buffer B (NHWC)
__device__ float    g_obj[NBOX*CC];       // per-box MLP output
__device__ unsigned g_mask[HWG*4];        // per-cell 128-bit box mask
__device__ float    g_wr[6*9*CC*CC];      // repacked weights [conv][tap][ci][co]
__device__ float    g_scale[6*CC];        // BN fused scale
__device__ float    g_bias[6*CC];         // BN fused bias

// ---------------- small prep kernels ----------------
__global__ void zero_mask_kernel() {
    int i = blockIdx.x * blockDim.x + threadIdx.x;
    int tot = HWG * 4;
    for (; i < tot; i += gridDim.x * blockDim.x) g_mask[i] = 0u;
}

// conv_w: (3,2,Cout,Cin,3,3) OIHW  ->  g_wr: [conv][tap][ci][co]
__global__ void repack_kernel(const float* __restrict__ cw) {
    int i = blockIdx.x * blockDim.x + threadIdx.x;
    if (i >= 6 * 9 * CC * CC) return;
    int co  = i & 255;
    int ci  = (i >> 8) & 255;
    int t9  = i >> 16;
    int tap = t9 % 9;
    int cv  = t9 / 9;
    g_wr[i] = cw[((cv * CC + co) * CC + ci) * 9 + tap];
}

__global__ void bnprep_kernel(const float* __restrict__ g, const float* __restrict__ b,
                              const float* __restrict__ m, const float* __restrict__ v) {
    int i = blockIdx.x * 256 + threadIdx.x;   // 6 blocks x 256
    float inv = g[i] / sqrtf(v[i] + 1e-5f);
    g_scale[i] = inv;
    g_bias[i]  = b[i] - m[i] * inv;
}

// ---------------- MLP: obj[n][c] ----------------
__global__ void mlp_kernel(const float* __restrict__ box, const float* __restrict__ score,
                           const float* __restrict__ w1, const float* __restrict__ b1,
                           const float* __restrict__ w2, const float* __restrict__ b2,
                           const float* __restrict__ w3, const float* __restrict__ b3) {
    int n = blockIdx.x;
    int c = threadIdx.x;
    __shared__ float feat[25];
    __shared__ float h1[CC];
    __shared__ float h2[CC];
    if (c < 24) feat[c] = box[n * 24 + c];
    if (c == 24) feat[24] = score[n];
    __syncthreads();
    float s = b1[c];
    #pragma unroll
    for (int k = 0; k < 25; k++) s += feat[k] * w1[k * CC + c];
    h1[c] = fmaxf(s, 0.f);
    __syncthreads();
    s = b2[c];
    for (int k = 0; k < CC; k++) s += h1[k] * w2[k * CC + c];
    h2[c] = fmaxf(s, 0.f);
    __syncthreads();
    s = b3[c];
    for (int k = 0; k < CC; k++) s += h2[k] * w3[k * CC + c];
    g_obj[n * CC + c] = s * score[n];
}

// ---------------- rasterize boxes into bitmask ----------------
__global__ void raster_kernel(const float* __restrict__ box) {
    int n = blockIdx.x;
    __shared__ float ax[4], ay[4], vx[4], vy[4];
    __shared__ int ilo, ihi, jlo, jhi;
    if (threadIdx.x == 0) {
        float gx[4], gy[4];
        float minx = 1e30f, maxx = -1e30f, miny = 1e30f, maxy = -1e30f;
        for (int e = 0; e < 4; e++) {
            gx[e] = (box[n * 24 + e * 3 + 0] - (-140.8f)) / 0.4f;
            gy[e] = (box[n * 24 + e * 3 + 1] - (-40.0f)) / 0.4f;
            minx = fminf(minx, gx[e]); maxx = fmaxf(maxx, gx[e]);
            miny = fminf(miny, gy[e]); maxy = fmaxf(maxy, gy[e]);
        }
        for (int e = 0; e < 4; e++) {
            ax[e] = gx[e]; ay[e] = gy[e];
            vx[e] = gx[(e + 1) & 3] - gx[e];
            vy[e] = gy[(e + 1) & 3] - gy[e];
        }
        int a = (int)floorf(minx - 0.5f); jlo = a < 0 ? 0 : a;
        int bq = (int)ceilf(maxx - 0.5f); jhi = bq > WG - 1 ? WG - 1 : bq;
        int c = (int)floorf(miny - 0.5f); ilo = c < 0 ? 0 : c;
        int d = (int)ceilf(maxy - 0.5f);  ihi = d > HG - 1 ? HG - 1 : d;
    }
    __syncthreads();
    int wspan = jhi - jlo + 1, hspan = ihi - ilo + 1;
    if (wspan <= 0 || hspan <= 0) return;
    int tot = wspan * hspan;
    unsigned bit = 1u << (n & 31);
    int word = n >> 5;
    for (int t = threadIdx.x; t < tot; t += blockDim.x) {
        int i = ilo + t / wspan;
        int j = jlo + t % wspan;
        float cx = j + 0.5f, cy = i + 0.5f;
        bool ins = true;
        #pragma unroll
        for (int e = 0; e < 4; e++) {
            float cr = vx[e] * (cy - ay[e]) - vy[e] * (cx - ax[e]);
            ins = ins && (cr >= 0.f);
        }
        if (ins) atomicOr(&g_mask[(i * WG + j) * 4 + word], bit);
    }
}

// ---------------- scatter: build x0 (NHWC) into g_A ----------------
__global__ void scatter_kernel() {
    int c = threadIdx.x;
    for (int cell = blockIdx.x; cell < HWG; cell += gridDim.x) {
        unsigned m[4];
        m[0] = g_mask[cell * 4 + 0];
        m[1] = g_mask[cell * 4 + 1];
        m[2] = g_mask[cell * 4 + 2];
        m[3] = g_mask[cell * 4 + 3];
        int cnt = __popc(m[0]) + __popc(m[1]) + __popc(m[2]) + __popc(m[3]);
        float s = 0.f;
        if (cnt) {
            #pragma unroll
            for (int w = 0; w < 4; w++) {
                unsigned bits = m[w];
                while (bits) {
                    int b = __ffs(bits) - 1;
                    bits &= bits - 1;
                    s += g_obj[(w * 32 + b) * CC + c];
                }
            }
            s = s / (float)cnt;
        }
        g_A[cell * CC + c] = s;
    }
}

// ---------------- conv3x3 + BN (+residual) + ReLU, NHWC fp32 ----------------
// Block tile: 8x8 pixels x 64 cout. Threads 256 = 16(co) x 16(pix-group).
// Each thread: 4 pixels (one row) x 4 couts.
__global__ void __launch_bounds__(256) conv_kernel(int cidx, int second) {
    const float* __restrict__ in  = second ? g_B : g_A;
    float*       __restrict__ out = second ? g_A : g_B;
    const float* __restrict__ wr  = g_wr + cidx * 9 * CC * CC;

    __shared__ __align__(16) float sIn[10][10][16];
    __shared__ __align__(16) float sW[9][16][64];

    int tid = threadIdx.x;
    int tx  = tid & 15;       // cout group
    int ty  = tid >> 4;       // pixel group
    int w0  = blockIdx.x * 8;
    int h0  = blockIdx.y * 8;
    int co0 = blockIdx.z * 64;
    int phb = ty >> 1;
    int pwb = (ty & 1) * 4;

    float acc[4][4];
    #pragma unroll
    for (int k = 0; k < 4; k++)
        #pragma unroll
        for (int c = 0; c < 4; c++) acc[k][c] = 0.f;

    for (int ci0 = 0; ci0 < CC; ci0 += 16) {
        // stage input halo tile 10x10x16
        for (int idx = tid; idx < 400; idx += 256) {
            int pos = idx >> 2, c4 = idx & 3;
            int hh = pos / 10, ww = pos - hh * 10;
            int gh = h0 + hh - 1, gw = w0 + ww - 1;
            float4 v = make_float4(0.f, 0.f, 0.f, 0.f);
            if (gh >= 0 && gh < HG && gw >= 0 && gw < WG)
                v = *(const float4*)&in[(gh * WG + gw) * CC + ci0 + c4 * 4];
            *(float4*)&sIn[hh][ww][c4 * 4] = v;
        }
        // stage weights 9x16x64
        for (int idx = tid; idx < 2304; idx += 256) {
            int co4 = idx & 15;
            int r   = idx >> 4;
            int ci  = r & 15;
            int tap = r >> 4;
            float4 v = *(const float4*)&wr[(tap * CC + ci0 + ci) * CC + co0 + co4 * 4];
            *(float4*)&sW[tap][ci][co4 * 4] = v;
        }
        __syncthreads();
        #pragma unroll 4
        for (int ci = 0; ci < 16; ci++) {
            #pragma unroll
            for (int tap = 0; tap < 9; tap++) {
                int dh = tap / 3, dw = tap - dh * 3;
                float4 wv = *(const float4*)&sW[tap][ci][tx * 4];
                #pragma unroll
                for (int k = 0; k < 4; k++) {
                    float xv = sIn[phb + dh][pwb + k + dw][ci];
                    acc[k][0] += xv * wv.x;
                    acc[k][1] += xv * wv.y;
                    acc[k][2] += xv * wv.z;
                    acc[k][3] += xv * wv.w;
                }
            }
        }
        __syncthreads();
    }

    float4 sc = *(const float4*)&g_scale[cidx * CC + co0 + tx * 4];
    float4 bs = *(const float4*)&g_bias [cidx * CC + co0 + tx * 4];
    #pragma unroll
    for (int k = 0; k < 4; k++) {
        int gh = h0 + phb, gw = w0 + pwb + k;
        int off = (gh * WG + gw) * CC + co0 + tx * 4;
        float4 v;
        v.x = acc[k][0] * sc.x + bs.x;
        v.y = acc[k][1] * sc.y + bs.y;
        v.z = acc[k][2] * sc.z + bs.z;
        v.w = acc[k][3] * sc.w + bs.w;
        if (second) {
            float4 r = *(const float4*)&g_A[off];   // residual (in-place safe: same thread)
            v.x += r.x; v.y += r.y; v.z += r.z; v.w += r.w;
        }
        v.x = fmaxf(v.x, 0.f); v.y = fmaxf(v.y, 0.f);
        v.z = fmaxf(v.z, 0.f); v.w = fmaxf(v.w, 0.f);
        *(float4*)&out[off] = v;
    }
}

// ---------------- NHWC -> CHW final transpose ----------------
__global__ void transpose_kernel(float* __restrict__ out) {
    __shared__ float t[32][33];
    int h  = blockIdx.z;
    int w0 = blockIdx.x * 32;
    int c0 = blockIdx.y * 32;
    #pragma unroll
    for (int r = 0; r < 4; r++) {
        int ww = threadIdx.y + r * 8;
        t[ww][threadIdx.x] = g_A[(h * WG + w0 + ww) * CC + c0 + threadIdx.x];
    }
    __syncthreads();
    #pragma unroll
    for (int r = 0; r < 4; r++) {
        int cc = threadIdx.y + r * 8;
        out[(c0 + cc) * HWG + h * WG + w0 + threadIdx.x] = t[threadIdx.x][cc];
    }
}

// ---------------- launch ----------------
extern "C" void kernel_launch(void* const* d_in, const int* in_sizes, int n_in,
                              void* d_out, int out_size) {
    const float* box    = (const float*)d_in[0];
    const float* score  = (const float*)d_in[1];
    const float* w1     = (const float*)d_in[2];
    const float* b1     = (const float*)d_in[3];
    const float* w2     = (const float*)d_in[4];
    const float* b2     = (const float*)d_in[5];
    const float* w3     = (const float*)d_in[6];
    const float* b3     = (const float*)d_in[7];
    const float* conv_w = (const float*)d_in[8];
    const float* bng    = (const float*)d_in[9];
    const float* bnb    = (const float*)d_in[10];
    const float* bnm    = (const float*)d_in[11];
    const float* bnv    = (const float*)d_in[12];
    float* out = (float*)d_out;

    zero_mask_kernel<<<550, 1024>>>();
    repack_kernel<<<(6 * 9 * CC * CC + 255) / 256, 256>>>(conv_w);
    bnprep_kernel<<<6, 256>>>(bng, bnb, bnm, bnv);
    mlp_kernel<<<NBOX, 256>>>(box, score, w1, b1, w2, b2, w3, b3);
    raster_kernel<<<NBOX, 256>>>(box);
    scatter_kernel<<<4096, 256>>>();

    for (int c = 0; c < 6; c++) {
        conv_kernel<<<dim3(WG / 8, HG / 8, 4), 256>>>(c, c & 1);
    }
    transpose_kernel<<<dim3(WG / 32, CC / 32, HG), dim3(32, 8)>>>(out);
}

// round 6
// speedup vs baseline: 2.3980x; 2.3940x over previous
#include <cuda_runtime.h>
#include <cuda_bf16.h>
#include <math.h>
#include <stdint.h>

#define HG 200
#define WG 704
#define HWG (HG*WG)
#define CC 256
#define NBOX 128

// ---------------- scratch ----------------
__device__ float          g_X[HWG*CC];
__device__ __nv_bfloat16  g_hi[2][HWG*CC];
__device__ __nv_bfloat16  g_lo[2][HWG*CC];
__device__ __nv_bfloat16  g_whi[6*9*CC*CC];   // [conv*9+tap][co][ci]
__device__ __nv_bfloat16  g_wlo[6*9*CC*CC];
__device__ float          g_obj[NBOX*CC];
__device__ unsigned       g_mask[HWG*4];
__device__ float          g_scale[6*CC];
__device__ float          g_bias[6*CC];

// ---------------- PTX helpers (all base-target sm_80/90 features) ----------------
__device__ __forceinline__ uint32_t smem_u32(const void* p) {
    uint32_t a;
    asm("{ .reg .u64 t; cvta.to.shared.u64 t, %1; cvt.u32.u64 %0, t; }" : "=r"(a) : "l"(p));
    return a;
}
__device__ __forceinline__ void cpa16(uint32_t dst, const void* src, bool valid) {
    uint32_t sz = valid ? 16u : 0u;
    asm volatile("cp.async.cg.shared.global [%0], [%1], 16, %2;"
                 :: "r"(dst), "l"(src), "r"(sz) : "memory");
}
__device__ __forceinline__ void cpa_commit() {
    asm volatile("cp.async.commit_group;" ::: "memory");
}
template <int N> __device__ __forceinline__ void cpa_wait() {
    asm volatile("cp.async.wait_group %0;" :: "n"(N) : "memory");
}
__device__ __forceinline__ void ldsm4(uint32_t* r, uint32_t addr) {
    asm volatile("ldmatrix.sync.aligned.m8n8.x4.shared.b16 {%0,%1,%2,%3}, [%4];"
                 : "=r"(r[0]), "=r"(r[1]), "=r"(r[2]), "=r"(r[3]) : "r"(addr));
}
__device__ __forceinline__ void mma16816(float* c, const uint32_t* a, uint32_t b0, uint32_t b1) {
    asm volatile("mma.sync.aligned.m16n8k16.row.col.f32.bf16.bf16.f32 "
                 "{%0,%1,%2,%3}, {%4,%5,%6,%7}, {%8,%9}, {%0,%1,%2,%3};"
                 : "+f"(c[0]), "+f"(c[1]), "+f"(c[2]), "+f"(c[3])
                 : "r"(a[0]), "r"(a[1]), "r"(a[2]), "r"(a[3]), "r"(b0), "r"(b1));
}

// ---------------- conv tiling ----------------
// Stage: A[2 halves][128 px][32 ci] rows of 80B; B[2][256 co][32 ci] rows of 80B
#define ROWB   80
#define A_HALF 10240            // 128*80
#define B_OFF  20480            // 2*A_HALF
#define B_HALF 20480            // 256*80
#define STAGE  61440            // B_OFF + 2*B_HALF
#define HDR    2048
#define SMEM_DYN (HDR + 2*STAGE)

// ---------------- prep kernels ----------------
__global__ void zero_mask_kernel() {
    int i = blockIdx.x * blockDim.x + threadIdx.x;
    for (; i < HWG * 4; i += gridDim.x * blockDim.x) g_mask[i] = 0u;
}

__global__ void repack_split(const float* __restrict__ cw) {
    int i = blockIdx.x * blockDim.x + threadIdx.x;
    if (i >= 6 * 9 * CC * CC) return;
    int ci  = i & 255;
    int co  = (i >> 8) & 255;
    int t9  = i >> 16;
    int tap = t9 % 9;
    int cv  = t9 / 9;
    float w = cw[((cv * CC + co) * CC + ci) * 9 + tap];
    __nv_bfloat16 h = __float2bfloat16(w);
    g_whi[i] = h;
    g_wlo[i] = __float2bfloat16(w - __bfloat162float(h));
}

__global__ void bnprep_kernel(const float* __restrict__ g, const float* __restrict__ b,
                              const float* __restrict__ m, const float* __restrict__ v) {
    int i = blockIdx.x * 256 + threadIdx.x;
    float inv = g[i] / sqrtf(v[i] + 1e-5f);
    g_scale[i] = inv;
    g_bias[i]  = b[i] - m[i] * inv;
}

__global__ void mlp_kernel(const float* __restrict__ box, const float* __restrict__ score,
                           const float* __restrict__ w1, const float* __restrict__ b1,
                           const float* __restrict__ w2, const float* __restrict__ b2,
                           const float* __restrict__ w3, const float* __restrict__ b3) {
    int n = blockIdx.x;
    int c = threadIdx.x;
    __shared__ float feat[25], h1[CC], h2[CC];
    if (c < 24) feat[c] = box[n * 24 + c];
    if (c == 24) feat[24] = score[n];
    __syncthreads();
    float s = b1[c];
    #pragma unroll
    for (int k = 0; k < 25; k++) s += feat[k] * w1[k * CC + c];
    h1[c] = fmaxf(s, 0.f);
    __syncthreads();
    s = b2[c];
    for (int k = 0; k < CC; k++) s += h1[k] * w2[k * CC + c];
    h2[c] = fmaxf(s, 0.f);
    __syncthreads();
    s = b3[c];
    for (int k = 0; k < CC; k++) s += h2[k] * w3[k * CC + c];
    g_obj[n * CC + c] = s * score[n];
}

__global__ void raster_kernel(const float* __restrict__ box) {
    int n = blockIdx.x;
    __shared__ float ax[4], ay[4], vx[4], vy[4];
    __shared__ int ilo, ihi, jlo, jhi;
    if (threadIdx.x == 0) {
        float gx[4], gy[4];
        float minx = 1e30f, maxx = -1e30f, miny = 1e30f, maxy = -1e30f;
        for (int e = 0; e < 4; e++) {
            gx[e] = (box[n * 24 + e * 3 + 0] + 140.8f) / 0.4f;
            gy[e] = (box[n * 24 + e * 3 + 1] + 40.0f) / 0.4f;
            minx = fminf(minx, gx[e]); maxx = fmaxf(maxx, gx[e]);
            miny = fminf(miny, gy[e]); maxy = fmaxf(maxy, gy[e]);
        }
        for (int e = 0; e < 4; e++) {
            ax[e] = gx[e]; ay[e] = gy[e];
            vx[e] = gx[(e + 1) & 3] - gx[e];
            vy[e] = gy[(e + 1) & 3] - gy[e];
        }
        int a = (int)floorf(minx - 0.5f); jlo = a < 0 ? 0 : a;
        int b2 = (int)ceilf(maxx - 0.5f); jhi = b2 > WG - 1 ? WG - 1 : b2;
        int c = (int)floorf(miny - 0.5f); ilo = c < 0 ? 0 : c;
        int d = (int)ceilf(maxy - 0.5f);  ihi = d > HG - 1 ? HG - 1 : d;
    }
    __syncthreads();
    int wspan = jhi - jlo + 1, hspan = ihi - ilo + 1;
    if (wspan <= 0 || hspan <= 0) return;
    unsigned bit = 1u << (n & 31);
    int word = n >> 5;
    for (int t = threadIdx.x; t < wspan * hspan; t += blockDim.x) {
        int i = ilo + t / wspan;
        int j = jlo + t % wspan;
        float cx = j + 0.5f, cy = i + 0.5f;
        bool ins = true;
        #pragma unroll
        for (int e = 0; e < 4; e++) {
            float cr = vx[e] * (cy - ay[e]) - vy[e] * (cx - ax[e]);
            ins = ins && (cr >= 0.f);
        }
        if (ins) atomicOr(&g_mask[(i * WG + j) * 4 + word], bit);
    }
}

__global__ void scatter_kernel() {
    int c = threadIdx.x;
    for (int cell = blockIdx.x; cell < HWG; cell += gridDim.x) {
        unsigned m0 = g_mask[cell*4+0], m1 = g_mask[cell*4+1];
        unsigned m2 = g_mask[cell*4+2], m3 = g_mask[cell*4+3];
        int cnt = __popc(m0) + __popc(m1) + __popc(m2) + __popc(m3);
        float s = 0.f;
        if (cnt) {
            unsigned mm[4] = {m0, m1, m2, m3};
            #pragma unroll
            for (int w = 0; w < 4; w++) {
                unsigned bits = mm[w];
                while (bits) {
                    int b = __ffs(bits) - 1;
                    bits &= bits - 1;
                    s += g_obj[(w * 32 + b) * CC + c];
                }
            }
            s /= (float)cnt;
        }
        g_X[cell * CC + c] = s;
        __nv_bfloat16 h = __float2bfloat16(s);
        g_hi[0][cell * CC + c] = h;
        g_lo[0][cell * CC + c] = __float2bfloat16(s - __bfloat162float(h));
    }
}

// ---------------- mma.sync implicit-GEMM conv ----------------
extern __shared__ char dsm[];

__device__ __forceinline__ void load_stage(int s, int buf, int cidx, int h, int w0,
                                           const __nv_bfloat16* inHi,
                                           const __nv_bfloat16* inLo) {
    int tap = s >> 3, ck = s & 7;
    int dh = tap / 3, dw = tap % 3;
    int gh = h + dh - 1;
    int ci0 = ck * 32;
    uint32_t base = smem_u32(dsm) + HDR + buf * STAGE;
    bool rowok = (gh >= 0) && (gh < HG);
    const __nv_bfloat16* wb = g_whi + (size_t)(cidx * 9 + tap) * CC * CC + ci0;
    const __nv_bfloat16* wl = g_wlo + (size_t)(cidx * 9 + tap) * CC * CC + ci0;
    for (int u = threadIdx.x; u < 3072; u += 512) {
        if (u < 1024) {                         // A: [half][128 px][4 x 16B]
            int half = u >> 9;
            int px = (u >> 2) & 127;
            int c = u & 3;
            int gw = w0 + dw - 1 + px;
            bool ok = rowok && (gw >= 0) && (gw < WG);
            const __nv_bfloat16* src = half ? inLo : inHi;
            size_t off = ok ? ((size_t)(gh * WG + gw) * CC + ci0 + c * 8) : 0;
            cpa16(base + half * A_HALF + px * ROWB + c * 16, src + off, ok);
        } else {                                // B: [half][256 co][4 x 16B]
            int v = u - 1024;
            int half = v >> 10;
            int co = (v >> 2) & 255;
            int c = v & 3;
            const __nv_bfloat16* src = (half ? wl : wb) + (size_t)co * CC + c * 8;
            cpa16(base + B_OFF + half * B_HALF + co * ROWB + c * 16, src, true);
        }
    }
}

__global__ void __launch_bounds__(512, 1) conv_mma(int cidx) {
    uint32_t sb = smem_u32(dsm);
    int tid = threadIdx.x;
    int w0 = blockIdx.x * 128;
    int h  = blockIdx.y;
    int inb = cidx & 1;
    int second = cidx & 1;
    const __nv_bfloat16* inHi = g_hi[inb];
    const __nv_bfloat16* inLo = g_lo[inb];
    __nv_bfloat16* outHi = g_hi[inb ^ 1];
    __nv_bfloat16* outLo = g_lo[inb ^ 1];
    float* sSc = (float*)dsm;
    float* sBs = (float*)(dsm + 1024);
    if (tid < 256) {
        sSc[tid] = g_scale[cidx * CC + tid];
        sBs[tid] = g_bias[cidx * CC + tid];
    }

    int lane = tid & 31, warp = tid >> 5;
    int wm0 = (warp & 3) * 32;          // M offset (px)
    int wn0 = (warp >> 2) * 64;         // N offset (co)
    // ldmatrix per-lane address components
    int laneRowA = lane & 15;               // A: lanes 0-15 rows, 16-31 k-hi
    int laneKA   = (lane >> 4) * 16;
    int laneRowB = (lane & 7) | (((lane >> 4) & 1) << 3);  // B: 0-7 n-lo,8-15 k-hi,16-23 n-hi...
    int laneKB   = ((lane >> 3) & 1) * 16;

    float acc[2][8][4];
    #pragma unroll
    for (int a = 0; a < 2; a++)
        #pragma unroll
        for (int b = 0; b < 8; b++)
            #pragma unroll
            for (int c = 0; c < 4; c++) acc[a][b][c] = 0.f;

    load_stage(0, 0, cidx, h, w0, inHi, inLo);
    cpa_commit();

    for (int s = 0; s < 72; s++) {
        if (s + 1 < 72) load_stage(s + 1, (s + 1) & 1, cidx, h, w0, inHi, inLo);
        cpa_commit();
        cpa_wait<1>();
        __syncthreads();
        uint32_t SBASE = sb + HDR + (s & 1) * STAGE;
        uint32_t aHi = SBASE,           aLo = SBASE + A_HALF;
        uint32_t bHi = SBASE + B_OFF,   bLo = SBASE + B_OFF + B_HALF;
        #pragma unroll
        for (int j = 0; j < 2; j++) {
            int kb = j * 32;
            uint32_t ah[2][4], al[2][4], bx[4][4];
            #pragma unroll
            for (int mi = 0; mi < 2; mi++)
                ldsm4(ah[mi], aHi + (wm0 + mi * 16 + laneRowA) * ROWB + kb + laneKA);
            #pragma unroll
            for (int nb = 0; nb < 4; nb++)
                ldsm4(bx[nb], bHi + (wn0 + nb * 16 + laneRowB) * ROWB + kb + laneKB);
            #pragma unroll
            for (int mi = 0; mi < 2; mi++)
                #pragma unroll
                for (int nb = 0; nb < 4; nb++) {
                    mma16816(acc[mi][2 * nb],     ah[mi], bx[nb][0], bx[nb][1]);
                    mma16816(acc[mi][2 * nb + 1], ah[mi], bx[nb][2], bx[nb][3]);
                }
            #pragma unroll
            for (int mi = 0; mi < 2; mi++)
                ldsm4(al[mi], aLo + (wm0 + mi * 16 + laneRowA) * ROWB + kb + laneKA);
            #pragma unroll
            for (int mi = 0; mi < 2; mi++)
                #pragma unroll
                for (int nb = 0; nb < 4; nb++) {
                    mma16816(acc[mi][2 * nb],     al[mi], bx[nb][0], bx[nb][1]);
                    mma16816(acc[mi][2 * nb + 1], al[mi], bx[nb][2], bx[nb][3]);
                }
            #pragma unroll
            for (int nb = 0; nb < 4; nb++)
                ldsm4(bx[nb], bLo + (wn0 + nb * 16 + laneRowB) * ROWB + kb + laneKB);
            #pragma unroll
            for (int mi = 0; mi < 2; mi++)
                #pragma unroll
                for (int nb = 0; nb < 4; nb++) {
                    mma16816(acc[mi][2 * nb],     ah[mi], bx[nb][0], bx[nb][1]);
                    mma16816(acc[mi][2 * nb + 1], ah[mi], bx[nb][2], bx[nb][3]);
                }
        }
        __syncthreads();
    }

    // epilogue: BN (+residual) + ReLU, write fp32 (odd convs) + bf16 hi/lo split
    int g = lane >> 2, tg = lane & 3;
    #pragma unroll
    for (int mi = 0; mi < 2; mi++) {
        #pragma unroll
        for (int half = 0; half < 2; half++) {
            int px = wm0 + mi * 16 + g + half * 8;
            int gw = w0 + px;
            if (gw < WG) {
                size_t pix = (size_t)(h * WG + gw) * CC;
                #pragma unroll
                for (int ni = 0; ni < 8; ni++) {
                    int co = wn0 + ni * 8 + tg * 2;
                    float v0 = acc[mi][ni][half * 2 + 0] * sSc[co]     + sBs[co];
                    float v1 = acc[mi][ni][half * 2 + 1] * sSc[co + 1] + sBs[co + 1];
                    if (second) {
                        float2 res = *(const float2*)&g_X[pix + co];
                        v0 = fmaxf(v0 + res.x, 0.f);
                        v1 = fmaxf(v1 + res.y, 0.f);
                        *(float2*)&g_X[pix + co] = make_float2(v0, v1);
                    } else {
                        v0 = fmaxf(v0, 0.f);
                        v1 = fmaxf(v1, 0.f);
                    }
                    __nv_bfloat16 h0 = __float2bfloat16(v0);
                    __nv_bfloat16 h1 = __float2bfloat16(v1);
                    __nv_bfloat162 hh; hh.x = h0; hh.y = h1;
                    __nv_bfloat162 ll;
                    ll.x = __float2bfloat16(v0 - __bfloat162float(h0));
                    ll.y = __float2bfloat16(v1 - __bfloat162float(h1));
                    *(__nv_bfloat162*)&outHi[pix + co] = hh;
                    *(__nv_bfloat162*)&outLo[pix + co] = ll;
                }
            }
        }
    }
}

// ---------------- final transpose NHWC(g_X) -> CHW ----------------
__global__ void transpose_kernel(float* __restrict__ out) {
    __shared__ float t[32][33];
    int h  = blockIdx.z;
    int w0 = blockIdx.x * 32;
    int c0 = blockIdx.y * 32;
    #pragma unroll
    for (int r = 0; r < 4; r++) {
        int ww = threadIdx.y + r * 8;
        t[ww][threadIdx.x] = g_X[(size_t)(h * WG + w0 + ww) * CC + c0 + threadIdx.x];
    }
    __syncthreads();
    #pragma unroll
    for (int r = 0; r < 4; r++) {
        int cc = threadIdx.y + r * 8;
        out[(size_t)(c0 + cc) * HWG + h * WG + w0 + threadIdx.x] = t[threadIdx.x][cc];
    }
}

// ---------------- launch ----------------
extern "C" void kernel_launch(void* const* d_in, const int* in_sizes, int n_in,
                              void* d_out, int out_size) {
    const float* box    = (const float*)d_in[0];
    const float* score  = (const float*)d_in[1];
    const float* w1     = (const float*)d_in[2];
    const float* b1     = (const float*)d_in[3];
    const float* w2     = (const float*)d_in[4];
    const float* b2     = (const float*)d_in[5];
    const float* w3     = (const float*)d_in[6];
    const float* b3     = (const float*)d_in[7];
    const float* conv_w = (const float*)d_in[8];
    const float* bng    = (const float*)d_in[9];
    const float* bnb    = (const float*)d_in[10];
    const float* bnm    = (const float*)d_in[11];
    const float* bnv    = (const float*)d_in[12];
    float* out = (float*)d_out;

    cudaFuncSetAttribute(conv_mma, cudaFuncAttributeMaxDynamicSharedMemorySize, SMEM_DYN);

    zero_mask_kernel<<<550, 1024>>>();
    repack_split<<<(6 * 9 * CC * CC + 255) / 256, 256>>>(conv_w);
    bnprep_kernel<<<6, 256>>>(bng, bnb, bnm, bnv);
    mlp_kernel<<<NBOX, 256>>>(box, score, w1, b1, w2, b2, w3, b3);
    raster_kernel<<<NBOX, 256>>>(box);
    scatter_kernel<<<4096, 256>>>();

    for (int c = 0; c < 6; c++)
        conv_mma<<<dim3((WG + 127) / 128, HG), 512, SMEM_DYN>>>(c);

    transpose_kernel<<<dim3(WG / 32, CC / 32, HG), dim3(32, 8)>>>(out);
}

// round 9
// speedup vs baseline: 3.8250x; 1.5951x over previous
#include <cuda_runtime.h>
#include <cuda_fp16.h>
#include <math.h>
#include <stdint.h>

#define HG 200
#define WG 704
#define HWG (HG*WG)
#define CC 256
#define NBOX 128

// ---------------- scratch ----------------
__device__ float   g_X[HWG*CC];
__device__ __half  g_hi[2][HWG*CC];
__device__ __half  g_lo[2][HWG*CC];
__device__ __half  g_wh[6*9*CC*CC];   // fp16 weights [conv*9+tap][co][ci]
__device__ float   g_obj[NBOX*CC];
__device__ unsigned g_mask[HWG*4];
__device__ float   g_scale[6*CC];
__device__ float   g_bias[6*CC];

// ---------------- PTX helpers ----------------
__device__ __forceinline__ uint32_t smem_u32(const void* p) {
    uint32_t a;
    asm("{ .reg .u64 t; cvta.to.shared.u64 t, %1; cvt.u32.u64 %0, t; }" : "=r"(a) : "l"(p));
    return a;
}
__device__ __forceinline__ void cpa16(uint32_t dst, const void* src, bool valid) {
    uint32_t sz = valid ? 16u : 0u;
    asm volatile("cp.async.cg.shared.global [%0], [%1], 16, %2;"
                 :: "r"(dst), "l"(src), "r"(sz) : "memory");
}
__device__ __forceinline__ void cpa_commit() {
    asm volatile("cp.async.commit_group;" ::: "memory");
}
template <int N> __device__ __forceinline__ void cpa_wait() {
    asm volatile("cp.async.wait_group %0;" :: "n"(N) : "memory");
}
__device__ __forceinline__ void ldsm4(uint32_t* r, uint32_t addr) {
    asm volatile("ldmatrix.sync.aligned.m8n8.x4.shared.b16 {%0,%1,%2,%3}, [%4];"
                 : "=r"(r[0]), "=r"(r[1]), "=r"(r[2]), "=r"(r[3]) : "r"(addr));
}
__device__ __forceinline__ void mma16816(float* c, const uint32_t* a, uint32_t b0, uint32_t b1) {
    asm volatile("mma.sync.aligned.m16n8k16.row.col.f32.f16.f16.f32 "
                 "{%0,%1,%2,%3}, {%4,%5,%6,%7}, {%8,%9}, {%0,%1,%2,%3};"
                 : "+f"(c[0]), "+f"(c[1]), "+f"(c[2]), "+f"(c[3])
                 : "r"(a[0]), "r"(a[1]), "r"(a[2]), "r"(a[3]), "r"(b0), "r"(b1));
}

// ---------------- conv tiling ----------------
// Stage (k=64): A[2 halves][128 px][64ci] rows of 144B; B[256 co][64ci] rows of 144B
#define ROWB   144
#define A_HALF 18432            // 128*144
#define B_OFF  36864            // 2*A_HALF
#define STAGE  73728            // B_OFF + 256*144
#define HDR    2048
#define SMEM_DYN (HDR + 2*STAGE)

// ---------------- prep kernels ----------------
__global__ void zero_mask_kernel() {
    int i = blockIdx.x * blockDim.x + threadIdx.x;
    for (; i < HWG * 4; i += gridDim.x * blockDim.x) g_mask[i] = 0u;
}

__global__ void repack_kernel(const float* __restrict__ cw) {
    int i = blockIdx.x * blockDim.x + threadIdx.x;
    if (i >= 6 * 9 * CC * CC) return;
    int ci  = i & 255;
    int co  = (i >> 8) & 255;
    int t9  = i >> 16;
    int tap = t9 % 9;
    int cv  = t9 / 9;
    g_wh[i] = __float2half(cw[((cv * CC + co) * CC + ci) * 9 + tap]);
}

__global__ void bnprep_kernel(const float* __restrict__ g, const float* __restrict__ b,
                              const float* __restrict__ m, const float* __restrict__ v) {
    int i = blockIdx.x * 256 + threadIdx.x;
    float inv = g[i] / sqrtf(v[i] + 1e-5f);
    g_scale[i] = inv;
    g_bias[i]  = b[i] - m[i] * inv;
}

__global__ void mlp_kernel(const float* __restrict__ box, const float* __restrict__ score,
                           const float* __restrict__ w1, const float* __restrict__ b1,
                           const float* __restrict__ w2, const float* __restrict__ b2,
                           const float* __restrict__ w3, const float* __restrict__ b3) {
    int n = blockIdx.x;
    int c = threadIdx.x;
    __shared__ float feat[25], h1[CC], h2[CC];
    if (c < 24) feat[c] = box[n * 24 + c];
    if (c == 24) feat[24] = score[n];
    __syncthreads();
    float s = b1[c];
    #pragma unroll
    for (int k = 0; k < 25; k++) s += feat[k] * w1[k * CC + c];
    h1[c] = fmaxf(s, 0.f);
    __syncthreads();
    s = b2[c];
    for (int k = 0; k < CC; k++) s += h1[k] * w2[k * CC + c];
    h2[c] = fmaxf(s, 0.f);
    __syncthreads();
    s = b3[c];
    for (int k = 0; k < CC; k++) s += h2[k] * w3[k * CC + c];
    g_obj[n * CC + c] = s * score[n];
}

__global__ void raster_kernel(const float* __restrict__ box) {
    int n = blockIdx.x;
    __shared__ float ax[4], ay[4], vx[4], vy[4];
    __shared__ int ilo, ihi, jlo, jhi;
    if (threadIdx.x == 0) {
        float gx[4], gy[4];
        float minx = 1e30f, maxx = -1e30f, miny = 1e30f, maxy = -1e30f;
        for (int e = 0; e < 4; e++) {
            gx[e] = (box[n * 24 + e * 3 + 0] + 140.8f) / 0.4f;
            gy[e] = (box[n * 24 + e * 3 + 1] + 40.0f) / 0.4f;
            minx = fminf(minx, gx[e]); maxx = fmaxf(maxx, gx[e]);
            miny = fminf(miny, gy[e]); maxy = fmaxf(maxy, gy[e]);
        }
        for (int e = 0; e < 4; e++) {
            ax[e] = gx[e]; ay[e] = gy[e];
            vx[e] = gx[(e + 1) & 3] - gx[e];
            vy[e] = gy[(e + 1) & 3] - gy[e];
        }
        int a = (int)floorf(minx - 0.5f); jlo = a < 0 ? 0 : a;
        int b2 = (int)ceilf(maxx - 0.5f); jhi = b2 > WG - 1 ? WG - 1 : b2;
        int c = (int)floorf(miny - 0.5f); ilo = c < 0 ? 0 : c;
        int d = (int)ceilf(maxy - 0.5f);  ihi = d > HG - 1 ? HG - 1 : d;
    }
    __syncthreads();
    int wspan = jhi - jlo + 1, hspan = ihi - ilo + 1;
    if (wspan <= 0 || hspan <= 0) return;
    unsigned bit = 1u << (n & 31);
    int word = n >> 5;
    for (int t = threadIdx.x; t < wspan * hspan; t += blockDim.x) {
        int i = ilo + t / wspan;
        int j = jlo + t % wspan;
        float cx = j + 0.5f, cy = i + 0.5f;
        bool ins = true;
        #pragma unroll
        for (int e = 0; e < 4; e++) {
            float cr = vx[e] * (cy - ay[e]) - vy[e] * (cx - ax[e]);
            ins = ins && (cr >= 0.f);
        }
        if (ins) atomicOr(&g_mask[(i * WG + j) * 4 + word], bit);
    }
}

__global__ void scatter_kernel() {
    int c = threadIdx.x;
    for (int cell = blockIdx.x; cell < HWG; cell += gridDim.x) {
        unsigned m0 = g_mask[cell*4+0], m1 = g_mask[cell*4+1];
        unsigned m2 = g_mask[cell*4+2], m3 = g_mask[cell*4+3];
        int cnt = __popc(m0) + __popc(m1) + __popc(m2) + __popc(m3);
        float s = 0.f;
        if (cnt) {
            unsigned mm[4] = {m0, m1, m2, m3};
            #pragma unroll
            for (int w = 0; w < 4; w++) {
                unsigned bits = mm[w];
                while (bits) {
                    int b = __ffs(bits) - 1;
                    bits &= bits - 1;
                    s += g_obj[(w * 32 + b) * CC + c];
                }
            }
            s /= (float)cnt;
        }
        g_X[cell * CC + c] = s;
        __half h = __float2half(s);
        g_hi[0][cell * CC + c] = h;
        g_lo[0][cell * CC + c] = __float2half(s - __half2float(h));
    }
}

// ---------------- mma.sync implicit-GEMM conv (fp16, A-split 2-pass) ----------------
extern __shared__ char dsm[];

__device__ __forceinline__ void load_stage(int s, int buf, int cidx, int h, int w0,
                                           const __half* inHi, const __half* inLo) {
    int tap = s >> 2, ck = s & 3;
    int dh = tap / 3, dw = tap % 3;
    int gh = h + dh - 1;
    int ci0 = ck * 64;
    uint32_t base = smem_u32(dsm) + HDR + buf * STAGE;
    bool rowok = (gh >= 0) && (gh < HG);
    const __half* wb = g_wh + (size_t)(cidx * 9 + tap) * CC * CC + ci0;
    for (int u = threadIdx.x; u < 4096; u += 512) {
        if (u < 2048) {                         // A: [half][128 px][8 x 16B]
            int half = u >> 10;
            int px = (u >> 3) & 127;
            int c = u & 7;
            int gw = w0 + dw - 1 + px;
            bool ok = rowok && (gw >= 0) && (gw < WG);
            const __half* src = half ? inLo : inHi;
            size_t off = ok ? ((size_t)(gh * WG + gw) * CC + ci0 + c * 8) : 0;
            cpa16(base + half * A_HALF + px * ROWB + c * 16, src + off, ok);
        } else {                                // B: [256 co][8 x 16B]
            int v = u - 2048;
            int co = v >> 3;
            int c = v & 7;
            cpa16(base + B_OFF + co * ROWB + c * 16, wb + (size_t)co * CC + c * 8, true);
        }
    }
}

__global__ void __launch_bounds__(512, 1) conv_mma(int cidx) {
    uint32_t sb = smem_u32(dsm);
    int tid = threadIdx.x;
    int w0 = blockIdx.x * 128;
    int h  = blockIdx.y;
    int inb = cidx & 1;
    int second = cidx & 1;
    const __half* inHi = g_hi[inb];
    const __half* inLo = g_lo[inb];
    __half* outHi = g_hi[inb ^ 1];
    __half* outLo = g_lo[inb ^ 1];
    float* sSc = (float*)dsm;
    float* sBs = (float*)(dsm + 1024);
    if (tid < 256) {
        sSc[tid] = g_scale[cidx * CC + tid];
        sBs[tid] = g_bias[cidx * CC + tid];
    }

    int lane = tid & 31, warp = tid >> 5;
    int wm0 = (warp & 3) * 32;          // M offset (px)
    int wn0 = (warp >> 2) * 64;         // N offset (co)
    int laneRowA = lane & 15;
    int laneKA   = (lane >> 4) * 16;
    int laneRowB = (lane & 7) | (((lane >> 4) & 1) << 3);
    int laneKB   = ((lane >> 3) & 1) * 16;

    float acc[2][8][4];
    #pragma unroll
    for (int a = 0; a < 2; a++)
        #pragma unroll
        for (int b = 0; b < 8; b++)
            #pragma unroll
            for (int c = 0; c < 4; c++) acc[a][b][c] = 0.f;

    load_stage(0, 0, cidx, h, w0, inHi, inLo);
    cpa_commit();

    for (int s = 0; s < 36; s++) {
        if (s + 1 < 36) load_stage(s + 1, (s + 1) & 1, cidx, h, w0, inHi, inLo);
        cpa_commit();
        cpa_wait<1>();
        __syncthreads();
        uint32_t SBASE = sb + HDR + (s & 1) * STAGE;
        uint32_t aHi = SBASE, aLo = SBASE + A_HALF, bHi = SBASE + B_OFF;
        #pragma unroll
        for (int j = 0; j < 4; j++) {
            int kb = j * 32;
            uint32_t ah[2][4], al[2][4], bx[4][4];
            #pragma unroll
            for (int mi = 0; mi < 2; mi++)
                ldsm4(ah[mi], aHi + (wm0 + mi * 16 + laneRowA) * ROWB + kb + laneKA);
            #pragma unroll
            for (int nb = 0; nb < 4; nb++)
                ldsm4(bx[nb], bHi + (wn0 + nb * 16 + laneRowB) * ROWB + kb + laneKB);
            #pragma unroll
            for (int mi = 0; mi < 2; mi++)
                #pragma unroll
                for (int nb = 0; nb < 4; nb++) {
                    mma16816(acc[mi][2 * nb],     ah[mi], bx[nb][0], bx[nb][1]);
                    mma16816(acc[mi][2 * nb + 1], ah[mi], bx[nb][2], bx[nb][3]);
                }
            #pragma unroll
            for (int mi = 0; mi < 2; mi++)
                ldsm4(al[mi], aLo + (wm0 + mi * 16 + laneRowA) * ROWB + kb + laneKA);
            #pragma unroll
            for (int mi = 0; mi < 2; mi++)
                #pragma unroll
                for (int nb = 0; nb < 4; nb++) {
                    mma16816(acc[mi][2 * nb],     al[mi], bx[nb][0], bx[nb][1]);
                    mma16816(acc[mi][2 * nb + 1], al[mi], bx[nb][2], bx[nb][3]);
                }
        }
        __syncthreads();
    }

    // epilogue: BN (+residual) + ReLU, fp32 state + fp16 hi/lo split for next conv
    int g = lane >> 2, tg = lane & 3;
    #pragma unroll
    for (int mi = 0; mi < 2; mi++) {
        #pragma unroll
        for (int half = 0; half < 2; half++) {
            int px = wm0 + mi * 16 + g + half * 8;
            int gw = w0 + px;
            if (gw < WG) {
                size_t pix = (size_t)(h * WG + gw) * CC;
                #pragma unroll
                for (int ni = 0; ni < 8; ni++) {
                    int co = wn0 + ni * 8 + tg * 2;
                    float v0 = acc[mi][ni][half * 2 + 0] * sSc[co]     + sBs[co];
                    float v1 = acc[mi][ni][half * 2 + 1] * sSc[co + 1] + sBs[co + 1];
                    if (second) {
                        float2 res = *(const float2*)&g_X[pix + co];
                        v0 = fmaxf(v0 + res.x, 0.f);
                        v1 = fmaxf(v1 + res.y, 0.f);
                        *(float2*)&g_X[pix + co] = make_float2(v0, v1);
                    } else {
                        v0 = fmaxf(v0, 0.f);
                        v1 = fmaxf(v1, 0.f);
                    }
                    __half h0 = __float2half(v0);
                    __half h1 = __float2half(v1);
                    __half2 hh; hh.x = h0; hh.y = h1;
                    __half2 ll;
                    ll.x = __float2half(v0 - __half2float(h0));
                    ll.y = __float2half(v1 - __half2float(h1));
                    *(__half2*)&outHi[pix + co] = hh;
                    *(__half2*)&outLo[pix + co] = ll;
                }
            }
        }
    }
}

// ---------------- final transpose NHWC(g_X) -> CHW ----------------
__global__ void transpose_kernel(float* __restrict__ out) {
    __shared__ float t[32][33];
    int h  = blockIdx.z;
    int w0 = blockIdx.x * 32;
    int c0 = blockIdx.y * 32;
    #pragma unroll
    for (int r = 0; r < 4; r++) {
        int ww = threadIdx.y + r * 8;
        t[ww][threadIdx.x] = g_X[(size_t)(h * WG + w0 + ww) * CC + c0 + threadIdx.x];
    }
    __syncthreads();
    #pragma unroll
    for (int r = 0; r < 4; r++) {
        int cc = threadIdx.y + r * 8;
        out[(size_t)(c0 + cc) * HWG + h * WG + w0 + threadIdx.x] = t[threadIdx.x][cc];
    }
}

// ---------------- launch ----------------
extern "C" void kernel_launch(void* const* d_in, const int* in_sizes, int n_in,
                              void* d_out, int out_size) {
    const float* box    = (const float*)d_in[0];
    const float* score  = (const float*)d_in[1];
    const float* w1     = (const float*)d_in[2];
    const float* b1     = (const float*)d_in[3];
    const float* w2     = (const float*)d_in[4];
    const float* b2     = (const float*)d_in[5];
    const float* w3     = (const float*)d_in[6];
    const float* b3     = (const float*)d_in[7];
    const float* conv_w = (const float*)d_in[8];
    const float* bng    = (const float*)d_in[9];
    const float* bnb    = (const float*)d_in[10];
    const float* bnm    = (const float*)d_in[11];
    const float* bnv    = (const float*)d_in[12];
    float* out = (float*)d_out;

    cudaFuncSetAttribute(conv_mma, cudaFuncAttributeMaxDynamicSharedMemorySize, SMEM_DYN);

    zero_mask_kernel<<<550, 1024>>>();
    repack_kernel<<<(6 * 9 * CC * CC + 255) / 256, 256>>>(conv_w);
    bnprep_kernel<<<6, 256>>>(bng, bnb, bnm, bnv);
    mlp_kernel<<<NBOX, 256>>>(box, score, w1, b1, w2, b2, w3, b3);
    raster_kernel<<<NBOX, 256>>>(box);
    scatter_kernel<<<4096, 256>>>();

    for (int c = 0; c < 6; c++)
        conv_mma<<<dim3((WG + 127) / 128, HG), 512, SMEM_DYN>>>(c);

    transpose_kernel<<<dim3(WG / 32, CC / 32, HG), dim3(32, 8)>>>(out);
}

// round 10
// speedup vs baseline: 3.9038x; 1.0206x over previous
#include <cuda_runtime.h>
#include <cuda_fp16.h>
#include <math.h>
#include <stdint.h>

#define HG 200
#define WG 704
#define HWG (HG*WG)
#define CC 256
#define NBOX 128

// ---------------- scratch ----------------
__device__ float    g_X[HWG*CC];
__device__ __half   g_hf[2][HWG*CC];      // fp16 activations (ping/pong)
__device__ __half   g_wh[6*9*CC*CC];      // fp16 weights [conv*9+tap][co][ci]
__device__ float    g_obj[NBOX*CC];
__device__ unsigned g_mask[HWG*4];
__device__ float    g_scale[6*CC];
__device__ float    g_bias[6*CC];

// ---------------- PTX helpers ----------------
__device__ __forceinline__ uint32_t smem_u32(const void* p) {
    uint32_t a;
    asm("{ .reg .u64 t; cvta.to.shared.u64 t, %1; cvt.u32.u64 %0, t; }" : "=r"(a) : "l"(p));
    return a;
}
__device__ __forceinline__ void cpa16(uint32_t dst, const void* src, bool valid) {
    uint32_t sz = valid ? 16u : 0u;
    asm volatile("cp.async.cg.shared.global [%0], [%1], 16, %2;"
                 :: "r"(dst), "l"(src), "r"(sz) : "memory");
}
__device__ __forceinline__ void cpa_commit() {
    asm volatile("cp.async.commit_group;" ::: "memory");
}
template <int N> __device__ __forceinline__ void cpa_wait() {
    asm volatile("cp.async.wait_group %0;" :: "n"(N) : "memory");
}
__device__ __forceinline__ void ldsm4(uint32_t* r, uint32_t addr) {
    asm volatile("ldmatrix.sync.aligned.m8n8.x4.shared.b16 {%0,%1,%2,%3}, [%4];"
                 : "=r"(r[0]), "=r"(r[1]), "=r"(r[2]), "=r"(r[3]) : "r"(addr));
}
__device__ __forceinline__ void mma16816(float* c, const uint32_t* a, uint32_t b0, uint32_t b1) {
    asm volatile("mma.sync.aligned.m16n8k16.row.col.f32.f16.f16.f32 "
                 "{%0,%1,%2,%3}, {%4,%5,%6,%7}, {%8,%9}, {%0,%1,%2,%3};"
                 : "+f"(c[0]), "+f"(c[1]), "+f"(c[2]), "+f"(c[3])
                 : "r"(a[0]), "r"(a[1]), "r"(a[2]), "r"(a[3]), "r"(b0), "r"(b1));
}

// ---------------- conv tiling ----------------
// Stage (k=64): A[128 px][64 ci] rows of 144B; B[256 co][64 ci] rows of 144B
#define ROWB   144
#define B_OFF  18432            // 128*144
#define STAGE  55296            // B_OFF + 256*144
#define HDR    2048
#define SMEM_DYN (HDR + 2*STAGE)

// ---------------- prep kernels ----------------
__global__ void zero_mask_kernel() {
    int i = blockIdx.x * blockDim.x + threadIdx.x;
    for (; i < HWG * 4; i += gridDim.x * blockDim.x) g_mask[i] = 0u;
}

__global__ void repack_kernel(const float* __restrict__ cw) {
    int i = blockIdx.x * blockDim.x + threadIdx.x;
    if (i >= 6 * 9 * CC * CC) return;
    int ci  = i & 255;
    int co  = (i >> 8) & 255;
    int t9  = i >> 16;
    int tap = t9 % 9;
    int cv  = t9 / 9;
    g_wh[i] = __float2half(cw[((cv * CC + co) * CC + ci) * 9 + tap]);
}

__global__ void bnprep_kernel(const float* __restrict__ g, const float* __restrict__ b,
                              const float* __restrict__ m, const float* __restrict__ v) {
    int i = blockIdx.x * 256 + threadIdx.x;
    float inv = g[i] / sqrtf(v[i] + 1e-5f);
    g_scale[i] = inv;
    g_bias[i]  = b[i] - m[i] * inv;
}

__global__ void mlp_kernel(const float* __restrict__ box, const float* __restrict__ score,
                           const float* __restrict__ w1, const float* __restrict__ b1,
                           const float* __restrict__ w2, const float* __restrict__ b2,
                           const float* __restrict__ w3, const float* __restrict__ b3) {
    int n = blockIdx.x;
    int c = threadIdx.x;
    __shared__ float feat[25], h1[CC], h2[CC];
    if (c < 24) feat[c] = box[n * 24 + c];
    if (c == 24) feat[24] = score[n];
    __syncthreads();
    float s = b1[c];
    #pragma unroll
    for (int k = 0; k < 25; k++) s += feat[k] * w1[k * CC + c];
    h1[c] = fmaxf(s, 0.f);
    __syncthreads();
    s = b2[c];
    for (int k = 0; k < CC; k++) s += h1[k] * w2[k * CC + c];
    h2[c] = fmaxf(s, 0.f);
    __syncthreads();
    s = b3[c];
    for (int k = 0; k < CC; k++) s += h2[k] * w3[k * CC + c];
    g_obj[n * CC + c] = s * score[n];
}

__global__ void raster_kernel(const float* __restrict__ box) {
    int n = blockIdx.x;
    __shared__ float ax[4], ay[4], vx[4], vy[4];
    __shared__ int ilo, ihi, jlo, jhi;
    if (threadIdx.x == 0) {
        float gx[4], gy[4];
        float minx = 1e30f, maxx = -1e30f, miny = 1e30f, maxy = -1e30f;
        for (int e = 0; e < 4; e++) {
            gx[e] = (box[n * 24 + e * 3 + 0] + 140.8f) / 0.4f;
            gy[e] = (box[n * 24 + e * 3 + 1] + 40.0f) / 0.4f;
            minx = fminf(minx, gx[e]); maxx = fmaxf(maxx, gx[e]);
            miny = fminf(miny, gy[e]); maxy = fmaxf(maxy, gy[e]);
        }
        for (int e = 0; e < 4; e++) {
            ax[e] = gx[e]; ay[e] = gy[e];
            vx[e] = gx[(e + 1) & 3] - gx[e];
            vy[e] = gy[(e + 1) & 3] - gy[e];
        }
        int a = (int)floorf(minx - 0.5f); jlo = a < 0 ? 0 : a;
        int b2 = (int)ceilf(maxx - 0.5f); jhi = b2 > WG - 1 ? WG - 1 : b2;
        int c = (int)floorf(miny - 0.5f); ilo = c < 0 ? 0 : c;
        int d = (int)ceilf(maxy - 0.5f);  ihi = d > HG - 1 ? HG - 1 : d;
    }
    __syncthreads();
    int wspan = jhi - jlo + 1, hspan = ihi - ilo + 1;
    if (wspan <= 0 || hspan <= 0) return;
    unsigned bit = 1u << (n & 31);
    int word = n >> 5;
    for (int t = threadIdx.x; t < wspan * hspan; t += blockDim.x) {
        int i = ilo + t / wspan;
        int j = jlo + t % wspan;
        float cx = j + 0.5f, cy = i + 0.5f;
        bool ins = true;
        #pragma unroll
        for (int e = 0; e < 4; e++) {
            float cr = vx[e] * (cy - ay[e]) - vy[e] * (cx - ax[e]);
            ins = ins && (cr >= 0.f);
        }
        if (ins) atomicOr(&g_mask[(i * WG + j) * 4 + word], bit);
    }
}

__global__ void scatter_kernel() {
    int c = threadIdx.x;
    for (int cell = blockIdx.x; cell < HWG; cell += gridDim.x) {
        unsigned m0 = g_mask[cell*4+0], m1 = g_mask[cell*4+1];
        unsigned m2 = g_mask[cell*4+2], m3 = g_mask[cell*4+3];
        int cnt = __popc(m0) + __popc(m1) + __popc(m2) + __popc(m3);
        float s = 0.f;
        if (cnt) {
            unsigned mm[4] = {m0, m1, m2, m3};
            #pragma unroll
            for (int w = 0; w < 4; w++) {
                unsigned bits = mm[w];
                while (bits) {
                    int b = __ffs(bits) - 1;
                    bits &= bits - 1;
                    s += g_obj[(w * 32 + b) * CC + c];
                }
            }
            s /= (float)cnt;
        }
        g_X[cell * CC + c] = s;
        g_hf[0][cell * CC + c] = __float2half(s);
    }
}

// ---------------- mma.sync implicit-GEMM conv (fp16 single-pass) ----------------
extern __shared__ char dsm[];

__device__ __forceinline__ void load_stage(int s, int buf, int cidx, int h, int w0,
                                           const __half* in) {
    int tap = s >> 2, ck = s & 3;
    int dh = tap / 3, dw = tap % 3;
    int gh = h + dh - 1;
    int ci0 = ck * 64;
    uint32_t base = smem_u32(dsm) + HDR + buf * STAGE;
    bool rowok = (gh >= 0) && (gh < HG);
    const __half* wb = g_wh + (size_t)(cidx * 9 + tap) * CC * CC + ci0;
    for (int u = threadIdx.x; u < 3072; u += 512) {
        if (u < 1024) {                         // A: [128 px][8 x 16B]
            int px = u >> 3;
            int c = u & 7;
            int gw = w0 + dw - 1 + px;
            bool ok = rowok && (gw >= 0) && (gw < WG);
            size_t off = ok ? ((size_t)(gh * WG + gw) * CC + ci0 + c * 8) : 0;
            cpa16(base + px * ROWB + c * 16, in + off, ok);
        } else {                                // B: [256 co][8 x 16B]
            int v = u - 1024;
            int co = v >> 3;
            int c = v & 7;
            cpa16(base + B_OFF + co * ROWB + c * 16, wb + (size_t)co * CC + c * 8, true);
        }
    }
}

__global__ void __launch_bounds__(512, 1) conv_mma(int cidx) {
    uint32_t sb = smem_u32(dsm);
    int tid = threadIdx.x;
    int w0 = blockIdx.x * 128;
    int h  = blockIdx.y;
    int inb = cidx & 1;
    int second = cidx & 1;
    const __half* in  = g_hf[inb];
    __half* outH = g_hf[inb ^ 1];
    float* sSc = (float*)dsm;
    float* sBs = (float*)(dsm + 1024);
    if (tid < 256) {
        sSc[tid] = g_scale[cidx * CC + tid];
        sBs[tid] = g_bias[cidx * CC + tid];
    }

    int lane = tid & 31, warp = tid >> 5;
    int wm0 = (warp & 3) * 32;          // M offset (px)
    int wn0 = (warp >> 2) * 64;         // N offset (co)
    int laneRowA = lane & 15;
    int laneKA   = (lane >> 4) * 16;
    int laneRowB = (lane & 7) | (((lane >> 4) & 1) << 3);
    int laneKB   = ((lane >> 3) & 1) * 16;

    float acc[2][8][4];
    #pragma unroll
    for (int a = 0; a < 2; a++)
        #pragma unroll
        for (int b = 0; b < 8; b++)
            #pragma unroll
            for (int c = 0; c < 4; c++) acc[a][b][c] = 0.f;

    load_stage(0, 0, cidx, h, w0, in);
    cpa_commit();

    for (int s = 0; s < 36; s++) {
        if (s + 1 < 36) load_stage(s + 1, (s + 1) & 1, cidx, h, w0, in);
        cpa_commit();
        cpa_wait<1>();
        __syncthreads();
        uint32_t SBASE = sb + HDR + (s & 1) * STAGE;
        uint32_t aT = SBASE, bT = SBASE + B_OFF;
        #pragma unroll
        for (int j = 0; j < 4; j++) {
            int kb = j * 32;
            uint32_t ah[2][4], bx[4][4];
            #pragma unroll
            for (int mi = 0; mi < 2; mi++)
                ldsm4(ah[mi], aT + (wm0 + mi * 16 + laneRowA) * ROWB + kb + laneKA);
            #pragma unroll
            for (int nb = 0; nb < 4; nb++)
                ldsm4(bx[nb], bT + (wn0 + nb * 16 + laneRowB) * ROWB + kb + laneKB);
            #pragma unroll
            for (int mi = 0; mi < 2; mi++)
                #pragma unroll
                for (int nb = 0; nb < 4; nb++) {
                    mma16816(acc[mi][2 * nb],     ah[mi], bx[nb][0], bx[nb][1]);
                    mma16816(acc[mi][2 * nb + 1], ah[mi], bx[nb][2], bx[nb][3]);
                }
        }
        __syncthreads();
    }

    // epilogue: BN (+residual) + ReLU, fp32 state + fp16 for next conv
    int g = lane >> 2, tg = lane & 3;
    #pragma unroll
    for (int mi = 0; mi < 2; mi++) {
        #pragma unroll
        for (int half = 0; half < 2; half++) {
            int px = wm0 + mi * 16 + g + half * 8;
            int gw = w0 + px;
            if (gw < WG) {
                size_t pix = (size_t)(h * WG + gw) * CC;
                #pragma unroll
                for (int ni = 0; ni < 8; ni++) {
                    int co = wn0 + ni * 8 + tg * 2;
                    float v0 = acc[mi][ni][half * 2 + 0] * sSc[co]     + sBs[co];
                    float v1 = acc[mi][ni][half * 2 + 1] * sSc[co + 1] + sBs[co + 1];
                    if (second) {
                        float2 res = *(const float2*)&g_X[pix + co];
                        v0 = fmaxf(v0 + res.x, 0.f);
                        v1 = fmaxf(v1 + res.y, 0.f);
                        *(float2*)&g_X[pix + co] = make_float2(v0, v1);
                    } else {
                        v0 = fmaxf(v0, 0.f);
                        v1 = fmaxf(v1, 0.f);
                    }
                    __half2 hh; hh.x = __float2half(v0); hh.y = __float2half(v1);
                    *(__half2*)&outH[pix + co] = hh;
                }
            }
        }
    }
}

// ---------------- final transpose NHWC(g_X) -> CHW ----------------
__global__ void transpose_kernel(float* __restrict__ out) {
    __shared__ float t[32][33];
    int h  = blockIdx.z;
    int w0 = blockIdx.x * 32;
    int c0 = blockIdx.y * 32;
    #pragma unroll
    for (int r = 0; r < 4; r++) {
        int ww = threadIdx.y + r * 8;
        t[ww][threadIdx.x] = g_X[(size_t)(h * WG + w0 + ww) * CC + c0 + threadIdx.x];
    }
    __syncthreads();
    #pragma unroll
    for (int r = 0; r < 4; r++) {
        int cc = threadIdx.y + r * 8;
        out[(size_t)(c0 + cc) * HWG + h * WG + w0 + threadIdx.x] = t[threadIdx.x][cc];
    }
}

// ---------------- launch ----------------
extern "C" void kernel_launch(void* const* d_in, const int* in_sizes, int n_in,
                              void* d_out, int out_size) {
    const float* box    = (const float*)d_in[0];
    const float* score  = (const float*)d_in[1];
    const float* w1     = (const float*)d_in[2];
    const float* b1     = (const float*)d_in[3];
    const float* w2     = (const float*)d_in[4];
    const float* b2     = (const float*)d_in[5];
    const float* w3     = (const float*)d_in[6];
    const float* b3     = (const float*)d_in[7];
    const float* conv_w = (const float*)d_in[8];
    const float* bng    = (const float*)d_in[9];
    const float* bnb    = (const float*)d_in[10];
    const float* bnm    = (const float*)d_in[11];
    const float* bnv    = (const float*)d_in[12];
    float* out = (float*)d_out;

    cudaFuncSetAttribute(conv_mma, cudaFuncAttributeMaxDynamicSharedMemorySize, SMEM_DYN);

    zero_mask_kernel<<<550, 1024>>>();
    repack_kernel<<<(6 * 9 * CC * CC + 255) / 256, 256>>>(conv_w);
    bnprep_kernel<<<6, 256>>>(bng, bnb, bnm, bnv);
    mlp_kernel<<<NBOX, 256>>>(box, score, w1, b1, w2, b2, w3, b3);
    raster_kernel<<<NBOX, 256>>>(box);
    scatter_kernel<<<4096, 256>>>();

    for (int c = 0; c < 6; c++)
        conv_mma<<<dim3((WG + 127) / 128, HG), 512, SMEM_DYN>>>(c);

    transpose_kernel<<<dim3(WG / 32, CC / 32, HG), dim3(32, 8)>>>(out);
}

// round 12
// speedup vs baseline: 6.0130x; 1.5403x over previous
#include <cuda_runtime.h>
#include <cuda_fp16.h>
#include <math.h>
#include <stdint.h>

#define HG 200
#define WG 704
#define HWG (HG*WG)
#define CC 256
#define NBOX 128

// ---------------- scratch ----------------
__device__ float    g_X[HWG*CC];
__device__ __half   g_hf[2][HWG*CC];      // fp16 activations (ping/pong)
__device__ __half   g_wh[6*9*CC*CC];      // fp16 weights [conv*9+tap][co][ci]
__device__ float    g_obj[NBOX*CC];
__device__ unsigned g_mask[HWG*4];
__device__ float    g_scale[6*CC];
__device__ float    g_bias[6*CC];

// ---------------- PTX helpers ----------------
__device__ __forceinline__ uint32_t smem_u32(const void* p) {
    uint32_t a;
    asm("{ .reg .u64 t; cvta.to.shared.u64 t, %1; cvt.u32.u64 %0, t; }" : "=r"(a) : "l"(p));
    return a;
}
__device__ __forceinline__ void cpa16(uint32_t dst, const void* src, bool valid) {
    uint32_t sz = valid ? 16u : 0u;
    asm volatile("cp.async.cg.shared.global [%0], [%1], 16, %2;"
                 :: "r"(dst), "l"(src), "r"(sz) : "memory");
}
__device__ __forceinline__ void cpa_commit() {
    asm volatile("cp.async.commit_group;" ::: "memory");
}
template <int N> __device__ __forceinline__ void cpa_wait() {
    asm volatile("cp.async.wait_group %0;" :: "n"(N) : "memory");
}
__device__ __forceinline__ void ldsm4(uint32_t* r, uint32_t addr) {
    asm volatile("ldmatrix.sync.aligned.m8n8.x4.shared.b16 {%0,%1,%2,%3}, [%4];"
                 : "=r"(r[0]), "=r"(r[1]), "=r"(r[2]), "=r"(r[3]) : "r"(addr));
}
__device__ __forceinline__ void mma16816(float* c, const uint32_t* a, uint32_t b0, uint32_t b1) {
    asm volatile("mma.sync.aligned.m16n8k16.row.col.f32.f16.f16.f32 "
                 "{%0,%1,%2,%3}, {%4,%5,%6,%7}, {%8,%9}, {%0,%1,%2,%3};"
                 : "+f"(c[0]), "+f"(c[1]), "+f"(c[2]), "+f"(c[3])
                 : "r"(a[0]), "r"(a[1]), "r"(a[2]), "r"(a[3]), "r"(b0), "r"(b1));
}

// ---------------- conv tiling ----------------
// Stage (k=64): A[128 px][64 ci] rows of 144B; B[256 co][64 ci] rows of 144B
#define ROWB   144
#define B_OFF  18432            // 128*144
#define STAGE  55296            // B_OFF + 256*144
#define NBUF   3
#define HDR    2048
#define SMEM_DYN (HDR + NBUF*STAGE)

// ---------------- prep kernels ----------------
__global__ void zero_mask_kernel() {
    int i = blockIdx.x * blockDim.x + threadIdx.x;
    for (; i < HWG * 4; i += gridDim.x * blockDim.x) g_mask[i] = 0u;
}

__global__ void repack_kernel(const float* __restrict__ cw) {
    int i = blockIdx.x * blockDim.x + threadIdx.x;
    if (i >= 6 * 9 * CC * CC) return;
    int ci  = i & 255;
    int co  = (i >> 8) & 255;
    int t9  = i >> 16;
    int tap = t9 % 9;
    int cv  = t9 / 9;
    g_wh[i] = __float2half(cw[((cv * CC + co) * CC + ci) * 9 + tap]);
}

__global__ void bnprep_kernel(const float* __restrict__ g, const float* __restrict__ b,
                              const float* __restrict__ m, const float* __restrict__ v) {
    int i = blockIdx.x * 256 + threadIdx.x;
    float inv = g[i] / sqrtf(v[i] + 1e-5f);
    g_scale[i] = inv;
    g_bias[i]  = b[i] - m[i] * inv;
}

__global__ void mlp_kernel(const float* __restrict__ box, const float* __restrict__ score,
                           const float* __restrict__ w1, const float* __restrict__ b1,
                           const float* __restrict__ w2, const float* __restrict__ b2,
                           const float* __restrict__ w3, const float* __restrict__ b3) {
    int n = blockIdx.x;
    int c = threadIdx.x;
    __shared__ float feat[25], h1[CC], h2[CC];
    if (c < 24) feat[c] = box[n * 24 + c];
    if (c == 24) feat[24] = score[n];
    __syncthreads();
    float s = b1[c];
    #pragma unroll
    for (int k = 0; k < 25; k++) s += feat[k] * w1[k * CC + c];
    h1[c] = fmaxf(s, 0.f);
    __syncthreads();
    s = b2[c];
    for (int k = 0; k < CC; k++) s += h1[k] * w2[k * CC + c];
    h2[c] = fmaxf(s, 0.f);
    __syncthreads();
    s = b3[c];
    for (int k = 0; k < CC; k++) s += h2[k] * w3[k * CC + c];
    g_obj[n * CC + c] = s * score[n];
}

__global__ void raster_kernel(const float* __restrict__ box) {
    int n = blockIdx.x;
    __shared__ float ax[4], ay[4], vx[4], vy[4];
    __shared__ int ilo, ihi, jlo, jhi;
    if (threadIdx.x == 0) {
        float gx[4], gy[4];
        float minx = 1e30f, maxx = -1e30f, miny = 1e30f, maxy = -1e30f;
        for (int e = 0; e < 4; e++) {
            gx[e] = (box[n * 24 + e * 3 + 0] + 140.8f) / 0.4f;
            gy[e] = (box[n * 24 + e * 3 + 1] + 40.0f) / 0.4f;
            minx = fminf(minx, gx[e]); maxx = fmaxf(maxx, gx[e]);
            miny = fminf(miny, gy[e]); maxy = fmaxf(maxy, gy[e]);
        }
        for (int e = 0; e < 4; e++) {
            ax[e] = gx[e]; ay[e] = gy[e];
            vx[e] = gx[(e + 1) & 3] - gx[e];
            vy[e] = gy[(e + 1) & 3] - gy[e];
        }
        int a = (int)floorf(minx - 0.5f); jlo = a < 0 ? 0 : a;
        int b2 = (int)ceilf(maxx - 0.5f); jhi = b2 > WG - 1 ? WG - 1 : b2;
        int c = (int)floorf(miny - 0.5f); ilo = c < 0 ? 0 : c;
        int d = (int)ceilf(maxy - 0.5f);  ihi = d > HG - 1 ? HG - 1 : d;
    }
    __syncthreads();
    int wspan = jhi - jlo + 1, hspan = ihi - ilo + 1;
    if (wspan <= 0 || hspan <= 0) return;
    unsigned bit = 1u << (n & 31);
    int word = n >> 5;
    for (int t = threadIdx.x; t < wspan * hspan; t += blockDim.x) {
        int i = ilo + t / wspan;
        int j = jlo + t % wspan;
        float cx = j + 0.5f, cy = i + 0.5f;
        bool ins = true;
        #pragma unroll
        for (int e = 0; e < 4; e++) {
            float cr = vx[e] * (cy - ay[e]) - vy[e] * (cx - ax[e]);
            ins = ins && (cr >= 0.f);
        }
        if (ins) atomicOr(&g_mask[(i * WG + j) * 4 + word], bit);
    }
}

__global__ void scatter_kernel() {
    int c = threadIdx.x;
    for (int cell = blockIdx.x; cell < HWG; cell += gridDim.x) {
        unsigned m0 = g_mask[cell*4+0], m1 = g_mask[cell*4+1];
        unsigned m2 = g_mask[cell*4+2], m3 = g_mask[cell*4+3];
        int cnt = __popc(m0) + __popc(m1) + __popc(m2) + __popc(m3);
        float s = 0.f;
        if (cnt) {
            unsigned mm[4] = {m0, m1, m2, m3};
            #pragma unroll
            for (int w = 0; w < 4; w++) {
                unsigned bits = mm[w];
                while (bits) {
                    int b = __ffs(bits) - 1;
                    bits &= bits - 1;
                    s += g_obj[(w * 32 + b) * CC + c];
                }
            }
            s /= (float)cnt;
        }
        g_X[cell * CC + c] = s;
        g_hf[0][cell * CC + c] = __float2half(s);
    }
}

// ---------------- mma.sync implicit-GEMM conv (fp16, 3-stage pipeline) ----------------
extern __shared__ char dsm[];

__device__ __forceinline__ void load_stage(int s, int buf, int cidx, int h, int w0,
                                           const __half* in) {
    int tap = s >> 2, ck = s & 3;
    int dh = tap / 3, dw = tap % 3;
    int gh = h + dh - 1;
    int ci0 = ck * 64;
    uint32_t base = smem_u32(dsm) + HDR + buf * STAGE;
    bool rowok = (gh >= 0) && (gh < HG);
    const __half* wb = g_wh + (size_t)(cidx * 9 + tap) * CC * CC + ci0;
    for (int u = threadIdx.x; u < 3072; u += 512) {
        if (u < 1024) {                         // A: [128 px][8 x 16B]
            int px = u >> 3;
            int c = u & 7;
            int gw = w0 + dw - 1 + px;
            bool ok = rowok && (gw >= 0) && (gw < WG);
            size_t off = ok ? ((size_t)(gh * WG + gw) * CC + ci0 + c * 8) : 0;
            cpa16(base + px * ROWB + c * 16, in + off, ok);
        } else {                                // B: [256 co][8 x 16B]
            int v = u - 1024;
            int co = v >> 3;
            int c = v & 7;
            cpa16(base + B_OFF + co * ROWB + c * 16, wb + (size_t)co * CC + c * 8, true);
        }
    }
}

__global__ void __launch_bounds__(512, 1) conv_mma(int cidx) {
    uint32_t sb = smem_u32(dsm);
    int tid = threadIdx.x;
    int w0 = blockIdx.x * 128;
    int h  = blockIdx.y;
    int inb = cidx & 1;
    int second = cidx & 1;
    const __half* in  = g_hf[inb];
    __half* outH = g_hf[inb ^ 1];
    float* sSc = (float*)dsm;
    float* sBs = (float*)(dsm + 1024);
    if (tid < 256) {
        sSc[tid] = g_scale[cidx * CC + tid];
        sBs[tid] = g_bias[cidx * CC + tid];
    }

    int lane = tid & 31, warp = tid >> 5;
    int wm0 = (warp & 3) * 32;          // M offset (px)
    int wn0 = (warp >> 2) * 64;         // N offset (co)
    int laneRowA = lane & 15;
    int laneKA   = (lane >> 4) * 16;
    int laneRowB = (lane & 7) | (((lane >> 4) & 1) << 3);
    int laneKB   = ((lane >> 3) & 1) * 16;

    float acc[2][8][4];
    #pragma unroll
    for (int a = 0; a < 2; a++)
        #pragma unroll
        for (int b = 0; b < 8; b++)
            #pragma unroll
            for (int c = 0; c < 4; c++) acc[a][b][c] = 0.f;

    // prologue: fill buffers 0 and 1
    load_stage(0, 0, cidx, h, w0, in);
    cpa_commit();
    load_stage(1, 1, cidx, h, w0, in);
    cpa_commit();

    int bufC = 0;   // buffer holding stage s
    int bufL = 2;   // buffer to load stage s+2 into
    for (int s = 0; s < 36; s++) {
        // wait: group s complete (own copies); pending may include group s+1
        cpa_wait<1>();
        // single barrier: publishes group-s data to all threads AND guarantees
        // every warp finished reading buffer bufL (last used by stage s-1)
        __syncthreads();
        // issue load for stage s+2 into bufL (freed by the barrier above)
        if (s + 2 < 36) load_stage(s + 2, bufL, cidx, h, w0, in);
        cpa_commit();

        uint32_t SBASE = sb + HDR + bufC * STAGE;
        uint32_t aT = SBASE, bT = SBASE + B_OFF;
        #pragma unroll
        for (int j = 0; j < 4; j++) {
            int kb = j * 32;
            uint32_t ah[2][4], bx[4][4];
            #pragma unroll
            for (int mi = 0; mi < 2; mi++)
                ldsm4(ah[mi], aT + (wm0 + mi * 16 + laneRowA) * ROWB + kb + laneKA);
            #pragma unroll
            for (int nb = 0; nb < 4; nb++)
                ldsm4(bx[nb], bT + (wn0 + nb * 16 + laneRowB) * ROWB + kb + laneKB);
            #pragma unroll
            for (int mi = 0; mi < 2; mi++)
                #pragma unroll
                for (int nb = 0; nb < 4; nb++) {
                    mma16816(acc[mi][2 * nb],     ah[mi], bx[nb][0], bx[nb][1]);
                    mma16816(acc[mi][2 * nb + 1], ah[mi], bx[nb][2], bx[nb][3]);
                }
        }
        // rotate buffers: s+1 is in bufC's successor; freed buffer becomes load target
        bufC = bufC + 1 == NBUF ? 0 : bufC + 1;
        bufL = bufL + 1 == NBUF ? 0 : bufL + 1;
    }

    // epilogue: BN (+residual) + ReLU, fp32 state + fp16 for next conv
    int g = lane >> 2, tg = lane & 3;
    #pragma unroll
    for (int mi = 0; mi < 2; mi++) {
        #pragma unroll
        for (int half = 0; half < 2; half++) {
            int px = wm0 + mi * 16 + g + half * 8;
            int gw = w0 + px;
            if (gw < WG) {
                size_t pix = (size_t)(h * WG + gw) * CC;
                #pragma unroll
                for (int ni = 0; ni < 8; ni++) {
                    int co = wn0 + ni * 8 + tg * 2;
                    float v0 = acc[mi][ni][half * 2 + 0] * sSc[co]     + sBs[co];
                    float v1 = acc[mi][ni][half * 2 + 1] * sSc[co + 1] + sBs[co + 1];
                    if (second) {
                        float2 res = *(const float2*)&g_X[pix + co];
                        v0 = fmaxf(v0 + res.x, 0.f);
                        v1 = fmaxf(v1 + res.y, 0.f);
                        *(float2*)&g_X[pix + co] = make_float2(v0, v1);
                    } else {
                        v0 = fmaxf(v0, 0.f);
                        v1 = fmaxf(v1, 0.f);
                    }
                    __half2 hh; hh.x = __float2half(v0); hh.y = __float2half(v1);
                    *(__half2*)&outH[pix + co] = hh;
                }
            }
        }
    }
}

// ---------------- final transpose NHWC(g_X) -> CHW ----------------
__global__ void transpose_kernel(float* __restrict__ out) {
    __shared__ float t[32][33];
    int h  = blockIdx.z;
    int w0 = blockIdx.x * 32;
    int c0 = blockIdx.y * 32;
    #pragma unroll
    for (int r = 0; r < 4; r++) {
        int ww = threadIdx.y + r * 8;
        t[ww][threadIdx.x] = g_X[(size_t)(h * WG + w0 + ww) * CC + c0 + threadIdx.x];
    }
    __syncthreads();
    #pragma unroll
    for (int r = 0; r < 4; r++) {
        int cc = threadIdx.y + r * 8;
        out[(size_t)(c0 + cc) * HWG + h * WG + w0 + threadIdx.x] = t[threadIdx.x][cc];
    }
}

// ---------------- launch ----------------
extern "C" void kernel_launch(void* const* d_in, const int* in_sizes, int n_in,
                              void* d_out, int out_size) {
    const float* box    = (const float*)d_in[0];
    const float* score  = (const float*)d_in[1];
    const float* w1     = (const float*)d_in[2];
    const float* b1     = (const float*)d_in[3];
    const float* w2     = (const float*)d_in[4];
    const float* b2     = (const float*)d_in[5];
    const float* w3     = (const float*)d_in[6];
    const float* b3     = (const float*)d_in[7];
    const float* conv_w = (const float*)d_in[8];
    const float* bng    = (const float*)d_in[9];
    const float* bnb    = (const float*)d_in[10];
    const float* bnm    = (const float*)d_in[11];
    const float* bnv    = (const float*)d_in[12];
    float* out = (float*)d_out;

    cudaFuncSetAttribute(conv_mma, cudaFuncAttributeMaxDynamicSharedMemorySize, SMEM_DYN);

    zero_mask_kernel<<<550, 1024>>>();
    repack_kernel<<<(6 * 9 * CC * CC + 255) / 256, 256>>>(conv_w);
    bnprep_kernel<<<6, 256>>>(bng, bnb, bnm, bnv);
    mlp_kernel<<<NBOX, 256>>>(box, score, w1, b1, w2, b2, w3, b3);
    raster_kernel<<<NBOX, 256>>>(box);
    scatter_kernel<<<4096, 256>>>();

    for (int c = 0; c < 6; c++)
        conv_mma<<<dim3((WG + 127) / 128, HG), 512, SMEM_DYN>>>(c);

    transpose_kernel<<<dim3(WG / 32, CC / 32, HG), dim3(32, 8)>>>(out);
}

// round 15
// speedup vs baseline: 6.9095x; 1.1491x over previous
#include <cuda_runtime.h>
#include <cuda_fp16.h>
#include <math.h>
#include <stdint.h>

#define HG 200
#define WG 704
#define HWG (HG*WG)
#define CC 256
#define NBOX 128

// ---------------- scratch ----------------
__device__ float    g_X[HWG*CC];
__device__ __half   g_hf[2][HWG*CC];      // fp16 activations (ping/pong)
__device__ __half   g_wh[6*9*CC*CC];      // fp16 weights [conv*9+tap][co][ci]
__device__ float    g_obj[NBOX*CC];
__device__ unsigned g_mask[HWG*4];
__device__ float    g_scale[6*CC];
__device__ float    g_bias[6*CC];

// ---------------- PTX helpers ----------------
__device__ __forceinline__ uint32_t smem_u32(const void* p) {
    uint32_t a;
    asm("{ .reg .u64 t; cvta.to.shared.u64 t, %1; cvt.u32.u64 %0, t; }" : "=r"(a) : "l"(p));
    return a;
}
__device__ __forceinline__ void cpa16(uint32_t dst, const void* src, bool valid) {
    uint32_t sz = valid ? 16u : 0u;
    asm volatile("cp.async.cg.shared.global [%0], [%1], 16, %2;"
                 :: "r"(dst), "l"(src), "r"(sz) : "memory");
}
__device__ __forceinline__ void cpa_commit() {
    asm volatile("cp.async.commit_group;" ::: "memory");
}
template <int N> __device__ __forceinline__ void cpa_wait() {
    asm volatile("cp.async.wait_group %0;" :: "n"(N) : "memory");
}
__device__ __forceinline__ void ldsm4(uint32_t* r, uint32_t addr) {
    asm volatile("ldmatrix.sync.aligned.m8n8.x4.shared.b16 {%0,%1,%2,%3}, [%4];"
                 : "=r"(r[0]), "=r"(r[1]), "=r"(r[2]), "=r"(r[3]) : "r"(addr));
}
__device__ __forceinline__ void mma16816(float* c, const uint32_t* a, uint32_t b0, uint32_t b1) {
    asm volatile("mma.sync.aligned.m16n8k16.row.col.f32.f16.f16.f32 "
                 "{%0,%1,%2,%3}, {%4,%5,%6,%7}, {%8,%9}, {%0,%1,%2,%3};"
                 : "+f"(c[0]), "+f"(c[1]), "+f"(c[2]), "+f"(c[3])
                 : "r"(a[0]), "r"(a[1]), "r"(a[2]), "r"(a[3]), "r"(b0), "r"(b1));
}

// ---------------- conv tiling ----------------
// Stage (k=64): A[128 px][64 ci] rows of 144B; B[256 co][64 ci] rows of 144B
#define ROWB   144
#define B_OFF  18432            // 128*144
#define STAGE  55296            // B_OFF + 256*144
#define NBUF   4
#define HDR    2048
#define SMEM_DYN (HDR + NBUF*STAGE)   // 223232 B

// ---------------- prep kernels ----------------
__global__ void zero_mask_kernel() {
    int i = blockIdx.x * blockDim.x + threadIdx.x;
    for (; i < HWG * 4; i += gridDim.x * blockDim.x) g_mask[i] = 0u;
}

__global__ void repack_kernel(const float* __restrict__ cw) {
    int i = blockIdx.x * blockDim.x + threadIdx.x;
    if (i >= 6 * 9 * CC * CC) return;
    int ci  = i & 255;
    int co  = (i >> 8) & 255;
    int t9  = i >> 16;
    int tap = t9 % 9;
    int cv  = t9 / 9;
    g_wh[i] = __float2half(cw[((cv * CC + co) * CC + ci) * 9 + tap]);
}

__global__ void bnprep_kernel(const float* __restrict__ g, const float* __restrict__ b,
                              const float* __restrict__ m, const float* __restrict__ v) {
    int i = blockIdx.x * 256 + threadIdx.x;
    float inv = g[i] / sqrtf(v[i] + 1e-5f);
    g_scale[i] = inv;
    g_bias[i]  = b[i] - m[i] * inv;
}

__global__ void mlp_kernel(const float* __restrict__ box, const float* __restrict__ score,
                           const float* __restrict__ w1, const float* __restrict__ b1,
                           const float* __restrict__ w2, const float* __restrict__ b2,
                           const float* __restrict__ w3, const float* __restrict__ b3) {
    int n = blockIdx.x;
    int c = threadIdx.x;
    __shared__ float feat[25], h1[CC], h2[CC];
    if (c < 24) feat[c] = box[n * 24 + c];
    if (c == 24) feat[24] = score[n];
    __syncthreads();
    float s = b1[c];
    #pragma unroll
    for (int k = 0; k < 25; k++) s += feat[k] * w1[k * CC + c];
    h1[c] = fmaxf(s, 0.f);
    __syncthreads();
    s = b2[c];
    for (int k = 0; k < CC; k++) s += h1[k] * w2[k * CC + c];
    h2[c] = fmaxf(s, 0.f);
    __syncthreads();
    s = b3[c];
    for (int k = 0; k < CC; k++) s += h2[k] * w3[k * CC + c];
    g_obj[n * CC + c] = s * score[n];
}

__global__ void raster_kernel(const float* __restrict__ box) {
    int n = blockIdx.x;
    __shared__ float ax[4], ay[4], vx[4], vy[4];
    __shared__ int ilo, ihi, jlo, jhi;
    if (threadIdx.x == 0) {
        float gx[4], gy[4];
        float minx = 1e30f, maxx = -1e30f, miny = 1e30f, maxy = -1e30f;
        for (int e = 0; e < 4; e++) {
            gx[e] = (box[n * 24 + e * 3 + 0] + 140.8f) / 0.4f;
            gy[e] = (box[n * 24 + e * 3 + 1] + 40.0f) / 0.4f;
            minx = fminf(minx, gx[e]); maxx = fmaxf(maxx, gx[e]);
            miny = fminf(miny, gy[e]); maxy = fmaxf(maxy, gy[e]);
        }
        for (int e = 0; e < 4; e++) {
            ax[e] = gx[e]; ay[e] = gy[e];
            vx[e] = gx[(e + 1) & 3] - gx[e];
            vy[e] = gy[(e + 1) & 3] - gy[e];
        }
        int a = (int)floorf(minx - 0.5f); jlo = a < 0 ? 0 : a;
        int b2 = (int)ceilf(maxx - 0.5f); jhi = b2 > WG - 1 ? WG - 1 : b2;
        int c = (int)floorf(miny - 0.5f); ilo = c < 0 ? 0 : c;
        int d = (int)ceilf(maxy - 0.5f);  ihi = d > HG - 1 ? HG - 1 : d;
    }
    __syncthreads();
    int wspan = jhi - jlo + 1, hspan = ihi - ilo + 1;
    if (wspan <= 0 || hspan <= 0) return;
    unsigned bit = 1u << (n & 31);
    int word = n >> 5;
    for (int t = threadIdx.x; t < wspan * hspan; t += blockDim.x) {
        int i = ilo + t / wspan;
        int j = jlo + t % wspan;
        float cx = j + 0.5f, cy = i + 0.5f;
        bool ins = true;
        #pragma unroll
        for (int e = 0; e < 4; e++) {
            float cr = vx[e] * (cy - ay[e]) - vy[e] * (cx - ax[e]);
            ins = ins && (cr >= 0.f);
        }
        if (ins) atomicOr(&g_mask[(i * WG + j) * 4 + word], bit);
    }
}

__global__ void scatter_kernel() {
    int c = threadIdx.x;
    for (int cell = blockIdx.x; cell < HWG; cell += gridDim.x) {
        unsigned m0 = g_mask[cell*4+0], m1 = g_mask[cell*4+1];
        unsigned m2 = g_mask[cell*4+2], m3 = g_mask[cell*4+3];
        int cnt = __popc(m0) + __popc(m1) + __popc(m2) + __popc(m3);
        float s = 0.f;
        if (cnt) {
            unsigned mm[4] = {m0, m1, m2, m3};
            #pragma unroll
            for (int w = 0; w < 4; w++) {
                unsigned bits = mm[w];
                while (bits) {
                    int b = __ffs(bits) - 1;
                    bits &= bits - 1;
                    s += g_obj[(w * 32 + b) * CC + c];
                }
            }
            s /= (float)cnt;
        }
        g_X[cell * CC + c] = s;
        g_hf[0][cell * CC + c] = __float2half(s);
    }
}

// ---------------- mma.sync implicit-GEMM conv (fp16, 4-buffer paired pipeline) ----------------
extern __shared__ char dsm[];

__device__ __forceinline__ void load_stage(int s, int buf, int cidx, int h, int w0,
                                           const __half* in) {
    int tap = s >> 2, ck = s & 3;
    int dh = tap / 3, dw = tap % 3;
    int gh = h + dh - 1;
    int ci0 = ck * 64;
    uint32_t base = smem_u32(dsm) + HDR + buf * STAGE;
    bool rowok = (gh >= 0) && (gh < HG);
    const __half* wb = g_wh + (size_t)(cidx * 9 + tap) * CC * CC + ci0;
    for (int u = threadIdx.x; u < 3072; u += 512) {
        if (u < 1024) {                         // A: [128 px][8 x 16B]
            int px = u >> 3;
            int c = u & 7;
            int gw = w0 + dw - 1 + px;
            bool ok = rowok && (gw >= 0) && (gw < WG);
            size_t off = ok ? ((size_t)(gh * WG + gw) * CC + ci0 + c * 8) : 0;
            cpa16(base + px * ROWB + c * 16, in + off, ok);
        } else {                                // B: [256 co][8 x 16B]
            int v = u - 1024;
            int co = v >> 3;
            int c = v & 7;
            cpa16(base + B_OFF + co * ROWB + c * 16, wb + (size_t)co * CC + c * 8, true);
        }
    }
}

__device__ __forceinline__ void compute_stage(uint32_t SBASE, float acc[2][8][4],
                                              int wm0, int wn0,
                                              int laneRowA, int laneKA,
                                              int laneRowB, int laneKB) {
    uint32_t aT = SBASE, bT = SBASE + B_OFF;
    #pragma unroll
    for (int j = 0; j < 4; j++) {
        int kb = j * 32;
        uint32_t ah[2][4], bx[4][4];
        #pragma unroll
        for (int mi = 0; mi < 2; mi++)
            ldsm4(ah[mi], aT + (wm0 + mi * 16 + laneRowA) * ROWB + kb + laneKA);
        #pragma unroll
        for (int nb = 0; nb < 4; nb++)
            ldsm4(bx[nb], bT + (wn0 + nb * 16 + laneRowB) * ROWB + kb + laneKB);
        #pragma unroll
        for (int mi = 0; mi < 2; mi++)
            #pragma unroll
            for (int nb = 0; nb < 4; nb++) {
                mma16816(acc[mi][2 * nb],     ah[mi], bx[nb][0], bx[nb][1]);
                mma16816(acc[mi][2 * nb + 1], ah[mi], bx[nb][2], bx[nb][3]);
            }
    }
}

__global__ void __launch_bounds__(512, 1) conv_mma(int cidx, float* __restrict__ out) {
    uint32_t sb = smem_u32(dsm);
    int tid = threadIdx.x;
    int w0 = blockIdx.x * 128;
    int h  = blockIdx.y;
    int inb = cidx & 1;
    int second = cidx & 1;
    int last = (cidx == 5);
    const __half* in  = g_hf[inb];
    __half* outH = g_hf[inb ^ 1];
    float* sSc = (float*)dsm;
    float* sBs = (float*)(dsm + 1024);
    if (tid < 256) {
        sSc[tid] = g_scale[cidx * CC + tid];
        sBs[tid] = g_bias[cidx * CC + tid];
    }

    int lane = tid & 31, warp = tid >> 5;
    int wm0 = (warp & 3) * 32;          // M offset (px)
    int wn0 = (warp >> 2) * 64;         // N offset (co)
    int laneRowA = lane & 15;
    int laneKA   = (lane >> 4) * 16;
    int laneRowB = (lane & 7) | (((lane >> 4) & 1) << 3);
    int laneKB   = ((lane >> 3) & 1) * 16;

    float acc[2][8][4];
    #pragma unroll
    for (int a = 0; a < 2; a++)
        #pragma unroll
        for (int b = 0; b < 8; b++)
            #pragma unroll
            for (int c = 0; c < 4; c++) acc[a][b][c] = 0.f;

    // prologue: fill buffers 0 and 1
    load_stage(0, 0, cidx, h, w0, in);
    cpa_commit();
    load_stage(1, 1, cidx, h, w0, in);
    cpa_commit();

    // 18 pairs of stages; ONE barrier per pair. The barrier frees the two
    // buffers read in the previous pair; loads for s+2 / s+3 target exactly
    // those (mod-4 rotation), staggered around compute(s0) to smooth L2 bursts.
    for (int p = 0; p < 18; p++) {
        int s0 = 2 * p, s1 = s0 + 1;
        cpa_wait<0>();          // groups s0, s1 landed (own copies)
        __syncthreads();        // publish + free buffers (s0+2)&3, (s1+2)&3
        if (s0 + 2 < 36) { load_stage(s0 + 2, (s0 + 2) & 3, cidx, h, w0, in); cpa_commit(); }
        compute_stage(sb + HDR + (s0 & 3) * STAGE, acc, wm0, wn0, laneRowA, laneKA, laneRowB, laneKB);
        if (s1 + 2 < 36) { load_stage(s1 + 2, (s1 + 2) & 3, cidx, h, w0, in); cpa_commit(); }
        compute_stage(sb + HDR + (s1 & 3) * STAGE, acc, wm0, wn0, laneRowA, laneKA, laneRowB, laneKB);
    }

    // epilogue: BN (+residual) + ReLU
    //  - convs 0..4: write fp32 state (odd convs) + fp16 activations for next conv
    //  - conv 5 (last): write CHW fp32 directly to d_out (transpose fused)
    int g = lane >> 2, tg = lane & 3;
    #pragma unroll
    for (int mi = 0; mi < 2; mi++) {
        #pragma unroll
        for (int half = 0; half < 2; half++) {
            int px = wm0 + mi * 16 + g + half * 8;
            int gw = w0 + px;
            if (gw < WG) {
                size_t pix = (size_t)(h * WG + gw) * CC;
                size_t hw  = (size_t)h * WG + gw;
                #pragma unroll
                for (int ni = 0; ni < 8; ni++) {
                    int co = wn0 + ni * 8 + tg * 2;
                    float v0 = acc[mi][ni][half * 2 + 0] * sSc[co]     + sBs[co];
                    float v1 = acc[mi][ni][half * 2 + 1] * sSc[co + 1] + sBs[co + 1];
                    if (second) {
                        float2 res = *(const float2*)&g_X[pix + co];
                        v0 = fmaxf(v0 + res.x, 0.f);
                        v1 = fmaxf(v1 + res.y, 0.f);
                        if (!last) *(float2*)&g_X[pix + co] = make_float2(v0, v1);
                    } else {
                        v0 = fmaxf(v0, 0.f);
                        v1 = fmaxf(v1, 0.f);
                    }
                    if (last) {
                        out[(size_t)co * HWG + hw]       = v0;
                        out[(size_t)(co + 1) * HWG + hw] = v1;
                    } else {
                        __half2 hh; hh.x = __float2half(v0); hh.y = __float2half(v1);
                        *(__half2*)&outH[pix + co] = hh;
                    }
                }
            }
        }
    }
}

// ---------------- launch ----------------
extern "C" void kernel_launch(void* const* d_in, const int* in_sizes, int n_in,
                              void* d_out, int out_size) {
    const float* box    = (const float*)d_in[0];
    const float* score  = (const float*)d_in[1];
    const float* w1     = (const float*)d_in[2];
    const float* b1     = (const float*)d_in[3];
    const float* w2     = (const float*)d_in[4];
    const float* b2     = (const float*)d_in[5];
    const float* w3     = (const float*)d_in[6];
    const float* b3     = (const float*)d_in[7];
    const float* conv_w = (const float*)d_in[8];
    const float* bng    = (const float*)d_in[9];
    const float* bnb    = (const float*)d_in[10];
    const float* bnm    = (const float*)d_in[11];
    const float* bnv    = (const float*)d_in[12];
    float* out = (float*)d_out;

    cudaFuncSetAttribute(conv_mma, cudaFuncAttributeMaxDynamicSharedMemorySize, SMEM_DYN);

    zero_mask_kernel<<<550, 1024>>>();
    repack_kernel<<<(6 * 9 * CC * CC + 255) / 256, 256>>>(conv_w);
    bnprep_kernel<<<6, 256>>>(bng, bnb, bnm, bnv);
    mlp_kernel<<<NBOX, 256>>>(box, score, w1, b1, w2, b2, w3, b3);
    raster_kernel<<<NBOX, 256>>>(box);
    scatter_kernel<<<4096, 256>>>();

    for (int c = 0; c < 6; c++)
        conv_mma<<<dim3((WG + 127) / 128, HG), 512, SMEM_DYN>>>(c, out);
}